// round 1
// baseline (speedup 1.0000x reference)
#include <cuda_runtime.h>
#include <math.h>

#define D 768
#define N_MAX 10000
#define E_RAW_MAX 100000
#define E_TOT_MAX (E_RAW_MAX + N_MAX)

// ---------------- scratch (device globals; no allocation allowed) ----------------
__device__ float g_h1[(size_t)N_MAX * D];   // x @ W1
__device__ float g_g [(size_t)N_MAX * D];   // relu(layer1 out)  (input of layer 2)
__device__ float g_h2[(size_t)N_MAX * D];   // g @ W2
__device__ float g_es[N_MAX];
__device__ float g_ed[N_MAX];
__device__ int   g_off[N_MAX + 1];
__device__ int   g_cur[N_MAX];
__device__ int   g_csr_src[E_TOT_MAX];

// ---------------- CSR build ----------------
__global__ void zero_cur_kernel(int n) {
    int i = blockIdx.x * blockDim.x + threadIdx.x;
    if (i < n) g_cur[i] = 0;
}

__global__ void hist_kernel(const int* __restrict__ ei, int e_raw, int n) {
    int e = blockIdx.x * blockDim.x + threadIdx.x;
    int e_tot = e_raw + n;
    if (e >= e_tot) return;
    int dst = (e < e_raw) ? ei[e_raw + e] : (e - e_raw);
    atomicAdd(&g_cur[dst], 1);
}

// single-block exclusive scan over g_cur[0..n) -> g_off, also reset g_cur = g_off (cursors)
__global__ void scan_kernel(int n) {
    __shared__ int sh[1024];
    __shared__ int s_carry;
    int tid = threadIdx.x;
    if (tid == 0) s_carry = 0;
    __syncthreads();
    for (int base = 0; base < n; base += 1024) {
        int i = base + tid;
        int v = (i < n) ? g_cur[i] : 0;
        sh[tid] = v;
        __syncthreads();
        for (int off = 1; off < 1024; off <<= 1) {
            int t = (tid >= off) ? sh[tid - off] : 0;
            __syncthreads();
            sh[tid] += t;
            __syncthreads();
        }
        int excl = sh[tid] - v;
        int carry = s_carry;
        if (i < n) { g_off[i] = carry + excl; g_cur[i] = carry + excl; }
        __syncthreads();
        if (tid == 1023) s_carry = carry + sh[1023];
        __syncthreads();
    }
    if (tid == 0) g_off[n] = s_carry;
}

__global__ void scatter_kernel(const int* __restrict__ ei, int e_raw, int n) {
    int e = blockIdx.x * blockDim.x + threadIdx.x;
    int e_tot = e_raw + n;
    if (e >= e_tot) return;
    int src = (e < e_raw) ? ei[e]         : (e - e_raw);
    int dst = (e < e_raw) ? ei[e_raw + e] : (e - e_raw);
    int pos = atomicAdd(&g_cur[dst], 1);
    g_csr_src[pos] = src;
}

// ---------------- GEMM: C[M,768] = A[M,768] @ B[768,768], fp32 ----------------
// 128x128 tile, K-tile 8, 256 threads, 8x8 per-thread microtile.
__global__ __launch_bounds__(256, 2)
void sgemm128_kernel(const float* __restrict__ A, const float* __restrict__ B,
                     float* __restrict__ C, int M) {
    __shared__ float As[8][128];
    __shared__ float Bs[8][128];
    const int tid = threadIdx.x;
    const int m0 = blockIdx.y * 128;
    const int n0 = blockIdx.x * 128;
    const int tx = tid & 15;        // 0..15 -> 8 cols each
    const int ty = tid >> 4;        // 0..15 -> 8 rows each

    // A load mapping: 128 rows x 8 k -> 256 float4 (2 per row)
    const int a_m = tid >> 1;
    const int a_k = (tid & 1) * 4;
    // B load mapping: 8 k x 128 n -> 256 float4
    const int b_k = tid >> 5;
    const int b_n = (tid & 31) * 4;

    float acc[8][8];
#pragma unroll
    for (int i = 0; i < 8; i++)
#pragma unroll
        for (int j = 0; j < 8; j++) acc[i][j] = 0.f;

    for (int k0 = 0; k0 < 768; k0 += 8) {
        float4 av;
        int arow = m0 + a_m;
        if (arow < M) av = *(const float4*)(A + (size_t)arow * 768 + k0 + a_k);
        else          av = make_float4(0.f, 0.f, 0.f, 0.f);
        As[a_k + 0][a_m] = av.x;
        As[a_k + 1][a_m] = av.y;
        As[a_k + 2][a_m] = av.z;
        As[a_k + 3][a_m] = av.w;

        float4 bv = *(const float4*)(B + (size_t)(k0 + b_k) * 768 + n0 + b_n);
        *(float4*)(&Bs[b_k][b_n]) = bv;
        __syncthreads();

#pragma unroll
        for (int k = 0; k < 8; k++) {
            float4 a0 = *(const float4*)(&As[k][ty * 8]);
            float4 a1 = *(const float4*)(&As[k][ty * 8 + 4]);
            float4 b0 = *(const float4*)(&Bs[k][tx * 8]);
            float4 b1 = *(const float4*)(&Bs[k][tx * 8 + 4]);
            float ar[8] = {a0.x, a0.y, a0.z, a0.w, a1.x, a1.y, a1.z, a1.w};
            float br[8] = {b0.x, b0.y, b0.z, b0.w, b1.x, b1.y, b1.z, b1.w};
#pragma unroll
            for (int i = 0; i < 8; i++)
#pragma unroll
                for (int j = 0; j < 8; j++) acc[i][j] = fmaf(ar[i], br[j], acc[i][j]);
        }
        __syncthreads();
    }

#pragma unroll
    for (int i = 0; i < 8; i++) {
        int m = m0 + ty * 8 + i;
        if (m < M) {
            float* crow = C + (size_t)m * 768 + n0 + tx * 8;
            *(float4*)(crow)     = make_float4(acc[i][0], acc[i][1], acc[i][2], acc[i][3]);
            *(float4*)(crow + 4) = make_float4(acc[i][4], acc[i][5], acc[i][6], acc[i][7]);
        }
    }
}

// ---------------- per-row attention logit dots: e_src[i]=h[i].a_src, e_dst[i]=h[i].a_dst ----------------
__global__ void dots_kernel(const float* __restrict__ h,
                            const float* __restrict__ a_src,
                            const float* __restrict__ a_dst, int n) {
    int warp = (blockIdx.x * blockDim.x + threadIdx.x) >> 5;
    int lane = threadIdx.x & 31;
    if (warp >= n) return;
    const float* row = h + (size_t)warp * D;
    float s = 0.f, d = 0.f;
#pragma unroll 4
    for (int i = lane; i < D; i += 32) {
        float v = row[i];
        s = fmaf(v, a_src[i], s);
        d = fmaf(v, a_dst[i], d);
    }
#pragma unroll
    for (int o = 16; o; o >>= 1) {
        s += __shfl_down_sync(0xffffffffu, s, o);
        d += __shfl_down_sync(0xffffffffu, d, o);
    }
    if (lane == 0) { g_es[warp] = s; g_ed[warp] = d; }
}

// ---------------- per-node segment softmax + weighted aggregation ----------------
// block = 256 threads, node = blockIdx.x. Each thread owns dims tid, tid+256, tid+512.
__global__ __launch_bounds__(256)
void agg_kernel(const float* __restrict__ h, const float* __restrict__ bias,
                float* __restrict__ out, int apply_relu) {
    const int node = blockIdx.x;
    const int tid = threadIdx.x;
    const int beg = g_off[node];
    const int end = g_off[node + 1];
    const float edv = g_ed[node];

    // pass 1: max logit
    float m = -1e30f;
    for (int i = beg + tid; i < end; i += 256) {
        float e = g_es[g_csr_src[i]] + edv;
        e = (e > 0.f) ? e : 0.2f * e;
        m = fmaxf(m, e);
    }
    __shared__ float red[256];
    red[tid] = m;
    __syncthreads();
#pragma unroll
    for (int o = 128; o; o >>= 1) {
        if (tid < o) red[tid] = fmaxf(red[tid], red[tid + o]);
        __syncthreads();
    }
    m = red[0];

    // pass 2: z = sum w, acc = sum w*h[src]
    float z = 0.f, a0 = 0.f, a1 = 0.f, a2 = 0.f;
    for (int i = beg; i < end; i++) {
        int s = __ldg(&g_csr_src[i]);
        float e = __ldg(&g_es[s]) + edv;
        e = (e > 0.f) ? e : 0.2f * e;
        float w = expf(e - m);
        z += w;
        const float* hr = h + (size_t)s * D;
        a0 = fmaf(w, __ldg(hr + tid),       a0);
        a1 = fmaf(w, __ldg(hr + tid + 256), a1);
        a2 = fmaf(w, __ldg(hr + tid + 512), a2);
    }
    float inv = 1.f / z;
    float o0 = fmaf(a0, inv, 0.f) + bias[tid];
    float o1 = fmaf(a1, inv, 0.f) + bias[tid + 256];
    float o2 = fmaf(a2, inv, 0.f) + bias[tid + 512];
    if (apply_relu) {
        o0 = fmaxf(o0, 0.f);
        o1 = fmaxf(o1, 0.f);
        o2 = fmaxf(o2, 0.f);
    }
    float* orow = out + (size_t)node * D;
    orow[tid]       = o0;
    orow[tid + 256] = o1;
    orow[tid + 512] = o2;
}

// ---------------- launch ----------------
extern "C" void kernel_launch(void* const* d_in, const int* in_sizes, int n_in,
                              void* d_out, int out_size) {
    const float* x   = (const float*)d_in[0];
    const int*   ei  = (const int*)  d_in[1];
    const float* W1  = (const float*)d_in[2];
    const float* as1 = (const float*)d_in[3];
    const float* ad1 = (const float*)d_in[4];
    const float* b1  = (const float*)d_in[5];
    const float* W2  = (const float*)d_in[6];
    const float* as2 = (const float*)d_in[7];
    const float* ad2 = (const float*)d_in[8];
    const float* b2  = (const float*)d_in[9];
    float* out = (float*)d_out;

    const int n     = in_sizes[0] / D;
    const int e_raw = in_sizes[1] / 2;
    const int e_tot = e_raw + n;

    float *h1, *g, *h2;
    cudaGetSymbolAddress((void**)&h1, g_h1);
    cudaGetSymbolAddress((void**)&g,  g_g);
    cudaGetSymbolAddress((void**)&h2, g_h2);

    // --- CSR by dst (with self loops appended) ---
    zero_cur_kernel<<<(n + 255) / 256, 256>>>(n);
    hist_kernel<<<(e_tot + 255) / 256, 256>>>(ei, e_raw, n);
    scan_kernel<<<1, 1024>>>(n);
    scatter_kernel<<<(e_tot + 255) / 256, 256>>>(ei, e_raw, n);

    dim3 gemm_grid(768 / 128, (n + 127) / 128);

    // --- layer 1 ---
    sgemm128_kernel<<<gemm_grid, 256>>>(x, W1, h1, n);
    dots_kernel<<<(n + 7) / 8, 256>>>(h1, as1, ad1, n);
    agg_kernel<<<n, 256>>>(h1, b1, g, 1);

    // --- layer 2 ---
    sgemm128_kernel<<<gemm_grid, 256>>>(g, W2, h2, n);
    dots_kernel<<<(n + 7) / 8, 256>>>(h2, as2, ad2, n);
    agg_kernel<<<n, 256>>>(h2, b2, out, 0);
}

// round 3
// speedup vs baseline: 2.2722x; 2.2722x over previous
#include <cuda_runtime.h>
#include <cuda_bf16.h>
#include <cstdint>
#include <math.h>

#define D 768
#define N_MAX 10000
#define E_RAW_MAX 100000
#define E_TOT_MAX (E_RAW_MAX + N_MAX)

// ---------------- scratch (device globals; no allocation allowed) ----------------
__device__ float g_h1[(size_t)N_MAX * D];
__device__ float g_h2[(size_t)N_MAX * D];
__device__ __nv_bfloat16 g_xh[(size_t)N_MAX * D];
__device__ __nv_bfloat16 g_xl[(size_t)N_MAX * D];
__device__ __nv_bfloat16 g_gh[(size_t)N_MAX * D];
__device__ __nv_bfloat16 g_gl[(size_t)N_MAX * D];
__device__ __nv_bfloat16 g_w1h[D * D], g_w1l[D * D];
__device__ __nv_bfloat16 g_w2h[D * D], g_w2l[D * D];
__device__ float g_es[N_MAX];
__device__ float g_ed[N_MAX];
__device__ int   g_off[N_MAX + 1];
__device__ int   g_cur[N_MAX];
__device__ int   g_csr_src[E_TOT_MAX];

// ================= helpers =================
__device__ __forceinline__ uint32_t smem_u32(const void* p) {
    uint32_t a;
    asm("{ .reg .u64 t; cvta.to.shared.u64 t, %1; cvt.u32.u64 %0, t; }" : "=r"(a) : "l"(p));
    return a;
}
// 128-byte XOR swizzle (rows of 128B, 16B granules)
__device__ __forceinline__ uint32_t sw128(uint32_t x) { return x ^ ((x >> 3) & 0x70); }

__device__ __forceinline__ void cp_async16(uint32_t dst, const void* src) {
    asm volatile("cp.async.cg.shared.global [%0], [%1], 16;" :: "r"(dst), "l"(src) : "memory");
}
__device__ __forceinline__ void ldsm4(uint32_t* r, uint32_t addr) {
    asm volatile("ldmatrix.sync.aligned.m8n8.x4.shared.b16 {%0,%1,%2,%3}, [%4];"
                 : "=r"(r[0]), "=r"(r[1]), "=r"(r[2]), "=r"(r[3]) : "r"(addr));
}
__device__ __forceinline__ void mma_bf16(float* c, const uint32_t* a, const uint32_t* b) {
    asm volatile("mma.sync.aligned.m16n8k16.row.col.f32.bf16.bf16.f32 "
                 "{%0,%1,%2,%3}, {%4,%5,%6,%7}, {%8,%9}, {%0,%1,%2,%3};"
                 : "+f"(c[0]), "+f"(c[1]), "+f"(c[2]), "+f"(c[3])
                 : "r"(a[0]), "r"(a[1]), "r"(a[2]), "r"(a[3]), "r"(b[0]), "r"(b[1]));
}

// ---------------- CSR build ----------------
__global__ void zero_cur_kernel(int n) {
    int i = blockIdx.x * blockDim.x + threadIdx.x;
    if (i < n) g_cur[i] = 0;
}
__global__ void hist_kernel(const int* __restrict__ ei, int e_raw, int n) {
    int e = blockIdx.x * blockDim.x + threadIdx.x;
    int e_tot = e_raw + n;
    if (e >= e_tot) return;
    int dst = (e < e_raw) ? ei[e_raw + e] : (e - e_raw);
    atomicAdd(&g_cur[dst], 1);
}
__global__ void scan_kernel(int n) {
    __shared__ int sh[1024];
    __shared__ int s_carry;
    int tid = threadIdx.x;
    if (tid == 0) s_carry = 0;
    __syncthreads();
    for (int base = 0; base < n; base += 1024) {
        int i = base + tid;
        int v = (i < n) ? g_cur[i] : 0;
        sh[tid] = v;
        __syncthreads();
        for (int off = 1; off < 1024; off <<= 1) {
            int t = (tid >= off) ? sh[tid - off] : 0;
            __syncthreads();
            sh[tid] += t;
            __syncthreads();
        }
        int excl = sh[tid] - v;
        int carry = s_carry;
        if (i < n) { g_off[i] = carry + excl; g_cur[i] = carry + excl; }
        __syncthreads();
        if (tid == 1023) s_carry = carry + sh[1023];
        __syncthreads();
    }
    if (tid == 0) g_off[n] = s_carry;
}
__global__ void scatter_kernel(const int* __restrict__ ei, int e_raw, int n) {
    int e = blockIdx.x * blockDim.x + threadIdx.x;
    int e_tot = e_raw + n;
    if (e >= e_tot) return;
    int src = (e < e_raw) ? ei[e]         : (e - e_raw);
    int dst = (e < e_raw) ? ei[e_raw + e] : (e - e_raw);
    int pos = atomicAdd(&g_cur[dst], 1);
    g_csr_src[pos] = src;
}

// ---------------- fp32 -> bf16 hi/lo split ----------------
__global__ void split_kernel(const float* __restrict__ x,
                             __nv_bfloat16* __restrict__ xh,
                             __nv_bfloat16* __restrict__ xl, int total) {
    int i = blockIdx.x * blockDim.x + threadIdx.x;
    if (i < total) {
        float v = x[i];
        __nv_bfloat16 h = __float2bfloat16(v);
        xh[i] = h;
        xl[i] = __float2bfloat16(v - __bfloat162float(h));
    }
}

// ---------------- W[k][n] -> Wt[n][k], split to bf16 hi/lo ----------------
__global__ void transpose_split_kernel(const float* __restrict__ W,
                                       __nv_bfloat16* __restrict__ Th,
                                       __nv_bfloat16* __restrict__ Tl) {
    __shared__ float sh[32][33];
    int n0 = blockIdx.x * 32, k0 = blockIdx.y * 32;
    int tx = threadIdx.x, ty = threadIdx.y;
#pragma unroll
    for (int j = 0; j < 32; j += 8)
        sh[ty + j][tx] = W[(size_t)(k0 + ty + j) * D + n0 + tx];
    __syncthreads();
#pragma unroll
    for (int j = 0; j < 32; j += 8) {
        float v = sh[tx][ty + j];
        __nv_bfloat16 h = __float2bfloat16(v);
        size_t idx = (size_t)(n0 + ty + j) * D + k0 + tx;
        Th[idx] = h;
        Tl[idx] = __float2bfloat16(v - __bfloat162float(h));
    }
}

// ---------------- tensor-core GEMM via mma.sync: C = (Ah+Al) @ (Bh+Bl)^T ----------------
// A splits: [M][768] row-major bf16. B splits: W^T [768 n][768 k] (K-contiguous).
// CTA tile 128x128, 8 warps (2 M x 4 N), warp tile 64x32, K-chunk 64, 2-stage cp.async.
// SMEM stage: Ah(16K) Al(16K) Bh(16K) Bl(16K) = 64KB; 2 stages = 128KB.
#define GEMM_SMEM (2 * 65536)

__global__ __launch_bounds__(256, 1)
void gemm_mma_kernel(const __nv_bfloat16* __restrict__ Ah,
                     const __nv_bfloat16* __restrict__ Al,
                     const __nv_bfloat16* __restrict__ Bh,
                     const __nv_bfloat16* __restrict__ Bl,
                     float* __restrict__ C, int M) {
    extern __shared__ __align__(1024) char smem[];
    const uint32_t sb = smem_u32(smem);
    const int tid  = threadIdx.x;
    const int wid  = tid >> 5;
    const int lane = tid & 31;
    const int m0 = blockIdx.y * 128;
    const int n0 = blockIdx.x * 128;
    const int warp_m = (wid & 1) * 64;
    const int warp_n = (wid >> 1) * 32;

    float acc[4][4][4];
#pragma unroll
    for (int i = 0; i < 4; i++)
#pragma unroll
        for (int j = 0; j < 4; j++)
#pragma unroll
            for (int k = 0; k < 4; k++) acc[i][j][k] = 0.f;

    // per-thread cp.async mapping: idx = i*256+tid -> row = idx>>3, cc = idx&7 (16B granule)
    auto issue_chunk = [&](int c) {
        const uint32_t st = sb + (uint32_t)(c & 1) * 65536;
        const int kc0 = c * 64;
#pragma unroll
        for (int i = 0; i < 4; i++) {
            int idx = i * 256 + tid;
            int row = idx >> 3, cc = idx & 7;
            uint32_t so = sw128((uint32_t)(row * 128 + cc * 16));
            int m = m0 + row; if (m >= M) m = M - 1;   // clamp: rows >= M never stored
            const size_t ga = (size_t)m * D + kc0 + cc * 8;
            cp_async16(st + 0     + so, Ah + ga);
            cp_async16(st + 16384 + so, Al + ga);
            const size_t gb = (size_t)(n0 + row) * D + kc0 + cc * 8;
            cp_async16(st + 32768 + so, Bh + gb);
            cp_async16(st + 49152 + so, Bl + gb);
        }
    };

    issue_chunk(0);
    asm volatile("cp.async.commit_group;" ::: "memory");

#pragma unroll 1
    for (int c = 0; c < 12; c++) {
        if (c + 1 < 12) {
            issue_chunk(c + 1);
            asm volatile("cp.async.commit_group;" ::: "memory");
            asm volatile("cp.async.wait_group 1;" ::: "memory");
        } else {
            asm volatile("cp.async.wait_group 0;" ::: "memory");
        }
        __syncthreads();

        const uint32_t st = sb + (uint32_t)(c & 1) * 65536;
#pragma unroll
        for (int ks = 0; ks < 4; ks++) {
            uint32_t afh[4][4], afl[4][4], bfh[2][4], bfl[2][4];
            // A fragments: 4 m-tiles of 16, ldmatrix.x4 each
            const int arow = lane & 15;
            const int acol = (ks * 16 + (lane >> 4) * 8) * 2;
#pragma unroll
            for (int mt = 0; mt < 4; mt++) {
                uint32_t off = sw128((uint32_t)((warp_m + mt * 16 + arow) * 128 + acol));
                ldsm4(afh[mt], st + 0     + off);
                ldsm4(afl[mt], st + 16384 + off);
            }
            // B fragments: 2 pairs of n-tiles (16 n-rows each)
            const int brow = (lane & 7) + ((lane >> 4) << 3);
            const int bcol = (ks * 16 + ((lane >> 3) & 1) * 8) * 2;
#pragma unroll
            for (int p = 0; p < 2; p++) {
                uint32_t off = sw128((uint32_t)((warp_n + p * 16 + brow) * 128 + bcol));
                ldsm4(bfh[p], st + 32768 + off);
                ldsm4(bfl[p], st + 49152 + off);
            }
#pragma unroll
            for (int mt = 0; mt < 4; mt++) {
#pragma unroll
                for (int nt = 0; nt < 4; nt++) {
                    const uint32_t* bh = &bfh[nt >> 1][(nt & 1) * 2];
                    const uint32_t* bl = &bfl[nt >> 1][(nt & 1) * 2];
                    mma_bf16(acc[mt][nt], afh[mt], bh);
                    mma_bf16(acc[mt][nt], afh[mt], bl);
                    mma_bf16(acc[mt][nt], afl[mt], bh);
                }
            }
        }
        __syncthreads();
    }

    // epilogue: c-frag m16n8 layout -> rows lane/4 (+8), cols (lane%4)*2
    const int er = lane >> 2;
    const int ec = (lane & 3) * 2;
#pragma unroll
    for (int mt = 0; mt < 4; mt++) {
#pragma unroll
        for (int nt = 0; nt < 4; nt++) {
            int row = m0 + warp_m + mt * 16 + er;
            int col = n0 + warp_n + nt * 8 + ec;
            if (row < M)
                *(float2*)(C + (size_t)row * D + col) = make_float2(acc[mt][nt][0], acc[mt][nt][1]);
            if (row + 8 < M)
                *(float2*)(C + (size_t)(row + 8) * D + col) = make_float2(acc[mt][nt][2], acc[mt][nt][3]);
        }
    }
}

// ---------------- per-row attention logit dots ----------------
__global__ void dots_kernel(const float* __restrict__ h,
                            const float* __restrict__ a_src,
                            const float* __restrict__ a_dst, int n) {
    int warp = (blockIdx.x * blockDim.x + threadIdx.x) >> 5;
    int lane = threadIdx.x & 31;
    if (warp >= n) return;
    const float* row = h + (size_t)warp * D;
    float s = 0.f, d = 0.f;
#pragma unroll 4
    for (int i = lane; i < D; i += 32) {
        float v = row[i];
        s = fmaf(v, a_src[i], s);
        d = fmaf(v, a_dst[i], d);
    }
#pragma unroll
    for (int o = 16; o; o >>= 1) {
        s += __shfl_down_sync(0xffffffffu, s, o);
        d += __shfl_down_sync(0xffffffffu, d, o);
    }
    if (lane == 0) { g_es[warp] = s; g_ed[warp] = d; }
}

// ---------------- segment softmax + aggregation (layer 1: emit bf16 split, relu) -------
__global__ __launch_bounds__(256)
void agg1_kernel(const float* __restrict__ h, const float* __restrict__ bias,
                 __nv_bfloat16* __restrict__ gh, __nv_bfloat16* __restrict__ gl) {
    const int node = blockIdx.x;
    const int tid = threadIdx.x;
    const int beg = g_off[node];
    const int end = g_off[node + 1];
    const float edv = g_ed[node];

    float mx = -1e30f;
    for (int i = beg + tid; i < end; i += 256) {
        float e = g_es[g_csr_src[i]] + edv;
        e = (e > 0.f) ? e : 0.2f * e;
        mx = fmaxf(mx, e);
    }
    __shared__ float red[256];
    red[tid] = mx;
    __syncthreads();
#pragma unroll
    for (int o = 128; o; o >>= 1) {
        if (tid < o) red[tid] = fmaxf(red[tid], red[tid + o]);
        __syncthreads();
    }
    mx = red[0];

    float z = 0.f, a0 = 0.f, a1 = 0.f, a2 = 0.f;
    for (int i = beg; i < end; i++) {
        int s = __ldg(&g_csr_src[i]);
        float e = __ldg(&g_es[s]) + edv;
        e = (e > 0.f) ? e : 0.2f * e;
        float w = expf(e - mx);
        z += w;
        const float* hr = h + (size_t)s * D;
        a0 = fmaf(w, __ldg(hr + tid),       a0);
        a1 = fmaf(w, __ldg(hr + tid + 256), a1);
        a2 = fmaf(w, __ldg(hr + tid + 512), a2);
    }
    float inv = 1.f / z;
    float o0 = fmaxf(a0 * inv + bias[tid],       0.f);
    float o1 = fmaxf(a1 * inv + bias[tid + 256], 0.f);
    float o2 = fmaxf(a2 * inv + bias[tid + 512], 0.f);
    size_t rb = (size_t)node * D;
    __nv_bfloat16 h0 = __float2bfloat16(o0);
    __nv_bfloat16 h1v = __float2bfloat16(o1);
    __nv_bfloat16 h2v = __float2bfloat16(o2);
    gh[rb + tid]       = h0;  gl[rb + tid]       = __float2bfloat16(o0 - __bfloat162float(h0));
    gh[rb + tid + 256] = h1v; gl[rb + tid + 256] = __float2bfloat16(o1 - __bfloat162float(h1v));
    gh[rb + tid + 512] = h2v; gl[rb + tid + 512] = __float2bfloat16(o2 - __bfloat162float(h2v));
}

// ---------------- segment softmax + aggregation (layer 2: fp32 out) ----------------
__global__ __launch_bounds__(256)
void agg2_kernel(const float* __restrict__ h, const float* __restrict__ bias,
                 float* __restrict__ out) {
    const int node = blockIdx.x;
    const int tid = threadIdx.x;
    const int beg = g_off[node];
    const int end = g_off[node + 1];
    const float edv = g_ed[node];

    float mx = -1e30f;
    for (int i = beg + tid; i < end; i += 256) {
        float e = g_es[g_csr_src[i]] + edv;
        e = (e > 0.f) ? e : 0.2f * e;
        mx = fmaxf(mx, e);
    }
    __shared__ float red[256];
    red[tid] = mx;
    __syncthreads();
#pragma unroll
    for (int o = 128; o; o >>= 1) {
        if (tid < o) red[tid] = fmaxf(red[tid], red[tid + o]);
        __syncthreads();
    }
    mx = red[0];

    float z = 0.f, a0 = 0.f, a1 = 0.f, a2 = 0.f;
    for (int i = beg; i < end; i++) {
        int s = __ldg(&g_csr_src[i]);
        float e = __ldg(&g_es[s]) + edv;
        e = (e > 0.f) ? e : 0.2f * e;
        float w = expf(e - mx);
        z += w;
        const float* hr = h + (size_t)s * D;
        a0 = fmaf(w, __ldg(hr + tid),       a0);
        a1 = fmaf(w, __ldg(hr + tid + 256), a1);
        a2 = fmaf(w, __ldg(hr + tid + 512), a2);
    }
    float inv = 1.f / z;
    float* orow = out + (size_t)node * D;
    orow[tid]       = a0 * inv + bias[tid];
    orow[tid + 256] = a1 * inv + bias[tid + 256];
    orow[tid + 512] = a2 * inv + bias[tid + 512];
}

// ---------------- launch ----------------
extern "C" void kernel_launch(void* const* d_in, const int* in_sizes, int n_in,
                              void* d_out, int out_size) {
    const float* x   = (const float*)d_in[0];
    const int*   ei  = (const int*)  d_in[1];
    const float* W1  = (const float*)d_in[2];
    const float* as1 = (const float*)d_in[3];
    const float* ad1 = (const float*)d_in[4];
    const float* b1  = (const float*)d_in[5];
    const float* W2  = (const float*)d_in[6];
    const float* as2 = (const float*)d_in[7];
    const float* ad2 = (const float*)d_in[8];
    const float* b2  = (const float*)d_in[9];
    float* out = (float*)d_out;

    const int n     = in_sizes[0] / D;
    const int e_raw = in_sizes[1] / 2;
    const int e_tot = e_raw + n;

    float *h1, *h2;
    __nv_bfloat16 *xh, *xl, *gh, *gl, *w1h, *w1l, *w2h, *w2l;
    cudaGetSymbolAddress((void**)&h1,  g_h1);
    cudaGetSymbolAddress((void**)&h2,  g_h2);
    cudaGetSymbolAddress((void**)&xh,  g_xh);
    cudaGetSymbolAddress((void**)&xl,  g_xl);
    cudaGetSymbolAddress((void**)&gh,  g_gh);
    cudaGetSymbolAddress((void**)&gl,  g_gl);
    cudaGetSymbolAddress((void**)&w1h, g_w1h);
    cudaGetSymbolAddress((void**)&w1l, g_w1l);
    cudaGetSymbolAddress((void**)&w2h, g_w2h);
    cudaGetSymbolAddress((void**)&w2l, g_w2l);

    cudaFuncSetAttribute(gemm_mma_kernel, cudaFuncAttributeMaxDynamicSharedMemorySize, GEMM_SMEM);

    // --- CSR by dst (with self loops appended) ---
    zero_cur_kernel<<<(n + 255) / 256, 256>>>(n);
    hist_kernel<<<(e_tot + 255) / 256, 256>>>(ei, e_raw, n);
    scan_kernel<<<1, 1024>>>(n);
    scatter_kernel<<<(e_tot + 255) / 256, 256>>>(ei, e_raw, n);

    // --- precision splits ---
    split_kernel<<<(n * D + 255) / 256, 256>>>(x, xh, xl, n * D);
    dim3 tgrid(D / 32, D / 32);
    transpose_split_kernel<<<tgrid, dim3(32, 8)>>>(W1, w1h, w1l);
    transpose_split_kernel<<<tgrid, dim3(32, 8)>>>(W2, w2h, w2l);

    dim3 gemm_grid(D / 128, (n + 127) / 128);

    // --- layer 1 ---
    gemm_mma_kernel<<<gemm_grid, 256, GEMM_SMEM>>>(xh, xl, w1h, w1l, h1, n);
    dots_kernel<<<(n + 7) / 8, 256>>>(h1, as1, ad1, n);
    agg1_kernel<<<n, 256>>>(h1, b1, gh, gl);

    // --- layer 2 ---
    gemm_mma_kernel<<<gemm_grid, 256, GEMM_SMEM>>>(gh, gl, w2h, w2l, h2, n);
    dots_kernel<<<(n + 7) / 8, 256>>>(h2, as2, ad2, n);
    agg2_kernel<<<n, 256>>>(h2, b2, out);
}

// round 4
// speedup vs baseline: 2.2987x; 1.0117x over previous
#include <cuda_runtime.h>
#include <cuda_bf16.h>
#include <cstdint>
#include <math.h>

#define D 768
#define N_MAX 10000
#define E_RAW_MAX 100000
#define E_TOT_MAX (E_RAW_MAX + N_MAX)

// ---------------- scratch (device globals; no allocation allowed) ----------------
__device__ float g_h1[(size_t)N_MAX * D];
__device__ float g_h2[(size_t)N_MAX * D];
__device__ __nv_bfloat16 g_xh[(size_t)N_MAX * D];
__device__ __nv_bfloat16 g_xl[(size_t)N_MAX * D];
__device__ __nv_bfloat16 g_gh[(size_t)N_MAX * D];
__device__ __nv_bfloat16 g_gl[(size_t)N_MAX * D];
__device__ __nv_bfloat16 g_w1h[D * D], g_w1l[D * D];
__device__ __nv_bfloat16 g_w2h[D * D], g_w2l[D * D];
__device__ float g_es1[N_MAX], g_ed1[N_MAX];
__device__ float g_es2[N_MAX], g_ed2[N_MAX];
__device__ int   g_off[N_MAX + 1];
__device__ int   g_cur[N_MAX];
__device__ int   g_csr_src[E_TOT_MAX];

// ================= helpers =================
__device__ __forceinline__ uint32_t smem_u32(const void* p) {
    uint32_t a;
    asm("{ .reg .u64 t; cvta.to.shared.u64 t, %1; cvt.u32.u64 %0, t; }" : "=r"(a) : "l"(p));
    return a;
}
__device__ __forceinline__ uint32_t sw128(uint32_t x) { return x ^ ((x >> 3) & 0x70); }

__device__ __forceinline__ void cp_async16(uint32_t dst, const void* src) {
    asm volatile("cp.async.cg.shared.global [%0], [%1], 16;" :: "r"(dst), "l"(src) : "memory");
}
__device__ __forceinline__ void ldsm4(uint32_t* r, uint32_t addr) {
    asm volatile("ldmatrix.sync.aligned.m8n8.x4.shared.b16 {%0,%1,%2,%3}, [%4];"
                 : "=r"(r[0]), "=r"(r[1]), "=r"(r[2]), "=r"(r[3]) : "r"(addr));
}
__device__ __forceinline__ void mma_bf16(float* c, const uint32_t* a, const uint32_t* b) {
    asm volatile("mma.sync.aligned.m16n8k16.row.col.f32.bf16.bf16.f32 "
                 "{%0,%1,%2,%3}, {%4,%5,%6,%7}, {%8,%9}, {%0,%1,%2,%3};"
                 : "+f"(c[0]), "+f"(c[1]), "+f"(c[2]), "+f"(c[3])
                 : "r"(a[0]), "r"(a[1]), "r"(a[2]), "r"(a[3]), "r"(b[0]), "r"(b[1]));
}

// ---------------- zero: cursors + dot accumulators ----------------
__global__ void zero_kernel(int n) {
    int i = blockIdx.x * blockDim.x + threadIdx.x;
    if (i < n) {
        g_cur[i] = 0;
        g_es1[i] = 0.f; g_ed1[i] = 0.f;
        g_es2[i] = 0.f; g_ed2[i] = 0.f;
    }
}
__global__ void hist_kernel(const int* __restrict__ ei, int e_raw, int n) {
    int e = blockIdx.x * blockDim.x + threadIdx.x;
    int e_tot = e_raw + n;
    if (e >= e_tot) return;
    int dst = (e < e_raw) ? ei[e_raw + e] : (e - e_raw);
    atomicAdd(&g_cur[dst], 1);
}
__global__ void scan_kernel(int n) {
    __shared__ int sh[1024];
    __shared__ int s_carry;
    int tid = threadIdx.x;
    if (tid == 0) s_carry = 0;
    __syncthreads();
    for (int base = 0; base < n; base += 1024) {
        int i = base + tid;
        int v = (i < n) ? g_cur[i] : 0;
        sh[tid] = v;
        __syncthreads();
        for (int off = 1; off < 1024; off <<= 1) {
            int t = (tid >= off) ? sh[tid - off] : 0;
            __syncthreads();
            sh[tid] += t;
            __syncthreads();
        }
        int excl = sh[tid] - v;
        int carry = s_carry;
        if (i < n) { g_off[i] = carry + excl; g_cur[i] = carry + excl; }
        __syncthreads();
        if (tid == 1023) s_carry = carry + sh[1023];
        __syncthreads();
    }
    if (tid == 0) g_off[n] = s_carry;
}
__global__ void scatter_kernel(const int* __restrict__ ei, int e_raw, int n) {
    int e = blockIdx.x * blockDim.x + threadIdx.x;
    int e_tot = e_raw + n;
    if (e >= e_tot) return;
    int src = (e < e_raw) ? ei[e]         : (e - e_raw);
    int dst = (e < e_raw) ? ei[e_raw + e] : (e - e_raw);
    int pos = atomicAdd(&g_cur[dst], 1);
    g_csr_src[pos] = src;
}

// ---------------- fp32 -> bf16 hi/lo split ----------------
__global__ void split_kernel(const float* __restrict__ x,
                             __nv_bfloat16* __restrict__ xh,
                             __nv_bfloat16* __restrict__ xl, int total) {
    int i = blockIdx.x * blockDim.x + threadIdx.x;
    if (i < total) {
        float v = x[i];
        __nv_bfloat16 h = __float2bfloat16(v);
        xh[i] = h;
        xl[i] = __float2bfloat16(v - __bfloat162float(h));
    }
}

// ---------------- W[k][n] -> Wt[n][k], split to bf16 hi/lo ----------------
__global__ void transpose_split_kernel(const float* __restrict__ W,
                                       __nv_bfloat16* __restrict__ Th,
                                       __nv_bfloat16* __restrict__ Tl) {
    __shared__ float sh[32][33];
    int n0 = blockIdx.x * 32, k0 = blockIdx.y * 32;
    int tx = threadIdx.x, ty = threadIdx.y;
#pragma unroll
    for (int j = 0; j < 32; j += 8)
        sh[ty + j][tx] = W[(size_t)(k0 + ty + j) * D + n0 + tx];
    __syncthreads();
#pragma unroll
    for (int j = 0; j < 32; j += 8) {
        float v = sh[tx][ty + j];
        __nv_bfloat16 h = __float2bfloat16(v);
        size_t idx = (size_t)(n0 + ty + j) * D + k0 + tx;
        Th[idx] = h;
        Tl[idx] = __float2bfloat16(v - __bfloat162float(h));
    }
}

// ---------------- tensor-core GEMM + fused attention dots ----------------
// C = (Ah+Al) @ (Bh+Bl)^T ; also es[m] += C[m,:].a_src, ed[m] += C[m,:].a_dst
// CTA tile 128x128, 8 warps (2M x 4N), warp tile 64x32, K-chunk 64, 3-stage cp.async.
#define GEMM_SMEM (3 * 65536)

__global__ __launch_bounds__(256, 1)
void gemm_mma_kernel(const __nv_bfloat16* __restrict__ Ah,
                     const __nv_bfloat16* __restrict__ Al,
                     const __nv_bfloat16* __restrict__ Bh,
                     const __nv_bfloat16* __restrict__ Bl,
                     float* __restrict__ C,
                     const float* __restrict__ a_src,
                     const float* __restrict__ a_dst,
                     float* __restrict__ es, float* __restrict__ ed,
                     int M) {
    extern __shared__ __align__(1024) char smem[];
    const uint32_t sb = smem_u32(smem);
    const int tid  = threadIdx.x;
    const int wid  = tid >> 5;
    const int lane = tid & 31;
    const int m0 = blockIdx.y * 128;
    const int n0 = blockIdx.x * 128;
    const int warp_m = (wid & 1) * 64;
    const int warp_n = (wid >> 1) * 32;

    float acc[4][4][4];
#pragma unroll
    for (int i = 0; i < 4; i++)
#pragma unroll
        for (int j = 0; j < 4; j++)
#pragma unroll
            for (int k = 0; k < 4; k++) acc[i][j][k] = 0.f;

    auto issue_chunk = [&](int c) {
        const uint32_t st = sb + (uint32_t)(c % 3) * 65536;
        const int kc0 = c * 64;
#pragma unroll
        for (int i = 0; i < 4; i++) {
            int idx = i * 256 + tid;
            int row = idx >> 3, cc = idx & 7;
            uint32_t so = sw128((uint32_t)(row * 128 + cc * 16));
            int m = m0 + row; if (m >= M) m = M - 1;   // clamp: rows >= M never stored
            const size_t ga = (size_t)m * D + kc0 + cc * 8;
            cp_async16(st + 0     + so, Ah + ga);
            cp_async16(st + 16384 + so, Al + ga);
            const size_t gb = (size_t)(n0 + row) * D + kc0 + cc * 8;
            cp_async16(st + 32768 + so, Bh + gb);
            cp_async16(st + 49152 + so, Bl + gb);
        }
    };

    issue_chunk(0);
    asm volatile("cp.async.commit_group;" ::: "memory");
    issue_chunk(1);
    asm volatile("cp.async.commit_group;" ::: "memory");

#pragma unroll 1
    for (int c = 0; c < 12; c++) {
        if (c + 2 < 12) {
            issue_chunk(c + 2);
            asm volatile("cp.async.commit_group;" ::: "memory");
            asm volatile("cp.async.wait_group 2;" ::: "memory");
        } else if (c + 1 < 12) {
            asm volatile("cp.async.wait_group 1;" ::: "memory");
        } else {
            asm volatile("cp.async.wait_group 0;" ::: "memory");
        }
        __syncthreads();

        const uint32_t st = sb + (uint32_t)(c % 3) * 65536;
#pragma unroll
        for (int ks = 0; ks < 4; ks++) {
            uint32_t afh[4][4], afl[4][4], bfh[2][4], bfl[2][4];
            const int arow = lane & 15;
            const int acol = (ks * 16 + (lane >> 4) * 8) * 2;
#pragma unroll
            for (int mt = 0; mt < 4; mt++) {
                uint32_t off = sw128((uint32_t)((warp_m + mt * 16 + arow) * 128 + acol));
                ldsm4(afh[mt], st + 0     + off);
                ldsm4(afl[mt], st + 16384 + off);
            }
            const int brow = (lane & 7) + ((lane >> 4) << 3);
            const int bcol = (ks * 16 + ((lane >> 3) & 1) * 8) * 2;
#pragma unroll
            for (int p = 0; p < 2; p++) {
                uint32_t off = sw128((uint32_t)((warp_n + p * 16 + brow) * 128 + bcol));
                ldsm4(bfh[p], st + 32768 + off);
                ldsm4(bfl[p], st + 49152 + off);
            }
#pragma unroll
            for (int mt = 0; mt < 4; mt++) {
#pragma unroll
                for (int nt = 0; nt < 4; nt++) {
                    const uint32_t* bh = &bfh[nt >> 1][(nt & 1) * 2];
                    const uint32_t* bl = &bfl[nt >> 1][(nt & 1) * 2];
                    mma_bf16(acc[mt][nt], afh[mt], bh);
                    mma_bf16(acc[mt][nt], afh[mt], bl);
                    mma_bf16(acc[mt][nt], afl[mt], bh);
                }
            }
        }
        __syncthreads();
    }

    // epilogue: store C + fused dot partials (quad shuffle reduce + atomicAdd)
    const int er = lane >> 2;
    const int ec = (lane & 3) * 2;
#pragma unroll
    for (int mt = 0; mt < 4; mt++) {
        int row = m0 + warp_m + mt * 16 + er;
        float s0 = 0.f, d0 = 0.f, s1 = 0.f, d1 = 0.f;
#pragma unroll
        for (int nt = 0; nt < 4; nt++) {
            int col = n0 + warp_n + nt * 8 + ec;
            if (row < M)
                *(float2*)(C + (size_t)row * D + col) = make_float2(acc[mt][nt][0], acc[mt][nt][1]);
            if (row + 8 < M)
                *(float2*)(C + (size_t)(row + 8) * D + col) = make_float2(acc[mt][nt][2], acc[mt][nt][3]);
            float as0 = __ldg(a_src + col), as1 = __ldg(a_src + col + 1);
            float ad0 = __ldg(a_dst + col), ad1 = __ldg(a_dst + col + 1);
            s0 = fmaf(acc[mt][nt][0], as0, fmaf(acc[mt][nt][1], as1, s0));
            d0 = fmaf(acc[mt][nt][0], ad0, fmaf(acc[mt][nt][1], ad1, d0));
            s1 = fmaf(acc[mt][nt][2], as0, fmaf(acc[mt][nt][3], as1, s1));
            d1 = fmaf(acc[mt][nt][2], ad0, fmaf(acc[mt][nt][3], ad1, d1));
        }
#pragma unroll
        for (int o = 1; o < 4; o <<= 1) {
            s0 += __shfl_xor_sync(0xffffffffu, s0, o);
            d0 += __shfl_xor_sync(0xffffffffu, d0, o);
            s1 += __shfl_xor_sync(0xffffffffu, s1, o);
            d1 += __shfl_xor_sync(0xffffffffu, d1, o);
        }
        if ((lane & 3) == 0) {
            if (row < M)     { atomicAdd(&es[row],     s0); atomicAdd(&ed[row],     d0); }
            if (row + 8 < M) { atomicAdd(&es[row + 8], s1); atomicAdd(&ed[row + 8], d1); }
        }
    }
}

// ---------------- segment softmax + aggregation (layer 1: emit bf16 split, relu) -------
__global__ __launch_bounds__(256)
void agg1_kernel(const float* __restrict__ h, const float* __restrict__ bias,
                 const float* __restrict__ es, const float* __restrict__ ed,
                 __nv_bfloat16* __restrict__ gh, __nv_bfloat16* __restrict__ gl) {
    const int node = blockIdx.x;
    const int tid = threadIdx.x;
    const int beg = g_off[node];
    const int end = g_off[node + 1];
    const float edv = ed[node];

    float mx = -1e30f;
    for (int i = beg + tid; i < end; i += 256) {
        float e = es[g_csr_src[i]] + edv;
        e = (e > 0.f) ? e : 0.2f * e;
        mx = fmaxf(mx, e);
    }
    __shared__ float red[256];
    red[tid] = mx;
    __syncthreads();
#pragma unroll
    for (int o = 128; o; o >>= 1) {
        if (tid < o) red[tid] = fmaxf(red[tid], red[tid + o]);
        __syncthreads();
    }
    mx = red[0];

    float z = 0.f, a0 = 0.f, a1 = 0.f, a2 = 0.f;
    for (int i = beg; i < end; i++) {
        int s = __ldg(&g_csr_src[i]);
        float e = __ldg(&es[s]) + edv;
        e = (e > 0.f) ? e : 0.2f * e;
        float w = expf(e - mx);
        z += w;
        const float* hr = h + (size_t)s * D;
        a0 = fmaf(w, __ldg(hr + tid),       a0);
        a1 = fmaf(w, __ldg(hr + tid + 256), a1);
        a2 = fmaf(w, __ldg(hr + tid + 512), a2);
    }
    float inv = 1.f / z;
    float o0 = fmaxf(a0 * inv + bias[tid],       0.f);
    float o1 = fmaxf(a1 * inv + bias[tid + 256], 0.f);
    float o2 = fmaxf(a2 * inv + bias[tid + 512], 0.f);
    size_t rb = (size_t)node * D;
    __nv_bfloat16 h0 = __float2bfloat16(o0);
    __nv_bfloat16 h1v = __float2bfloat16(o1);
    __nv_bfloat16 h2v = __float2bfloat16(o2);
    gh[rb + tid]       = h0;  gl[rb + tid]       = __float2bfloat16(o0 - __bfloat162float(h0));
    gh[rb + tid + 256] = h1v; gl[rb + tid + 256] = __float2bfloat16(o1 - __bfloat162float(h1v));
    gh[rb + tid + 512] = h2v; gl[rb + tid + 512] = __float2bfloat16(o2 - __bfloat162float(h2v));
}

// ---------------- segment softmax + aggregation (layer 2: fp32 out) ----------------
__global__ __launch_bounds__(256)
void agg2_kernel(const float* __restrict__ h, const float* __restrict__ bias,
                 const float* __restrict__ es, const float* __restrict__ ed,
                 float* __restrict__ out) {
    const int node = blockIdx.x;
    const int tid = threadIdx.x;
    const int beg = g_off[node];
    const int end = g_off[node + 1];
    const float edv = ed[node];

    float mx = -1e30f;
    for (int i = beg + tid; i < end; i += 256) {
        float e = es[g_csr_src[i]] + edv;
        e = (e > 0.f) ? e : 0.2f * e;
        mx = fmaxf(mx, e);
    }
    __shared__ float red[256];
    red[tid] = mx;
    __syncthreads();
#pragma unroll
    for (int o = 128; o; o >>= 1) {
        if (tid < o) red[tid] = fmaxf(red[tid], red[tid + o]);
        __syncthreads();
    }
    mx = red[0];

    float z = 0.f, a0 = 0.f, a1 = 0.f, a2 = 0.f;
    for (int i = beg; i < end; i++) {
        int s = __ldg(&g_csr_src[i]);
        float e = __ldg(&es[s]) + edv;
        e = (e > 0.f) ? e : 0.2f * e;
        float w = expf(e - mx);
        z += w;
        const float* hr = h + (size_t)s * D;
        a0 = fmaf(w, __ldg(hr + tid),       a0);
        a1 = fmaf(w, __ldg(hr + tid + 256), a1);
        a2 = fmaf(w, __ldg(hr + tid + 512), a2);
    }
    float inv = 1.f / z;
    float* orow = out + (size_t)node * D;
    orow[tid]       = a0 * inv + bias[tid];
    orow[tid + 256] = a1 * inv + bias[tid + 256];
    orow[tid + 512] = a2 * inv + bias[tid + 512];
}

// ---------------- launch ----------------
extern "C" void kernel_launch(void* const* d_in, const int* in_sizes, int n_in,
                              void* d_out, int out_size) {
    const float* x   = (const float*)d_in[0];
    const int*   ei  = (const int*)  d_in[1];
    const float* W1  = (const float*)d_in[2];
    const float* as1 = (const float*)d_in[3];
    const float* ad1 = (const float*)d_in[4];
    const float* b1  = (const float*)d_in[5];
    const float* W2  = (const float*)d_in[6];
    const float* as2 = (const float*)d_in[7];
    const float* ad2 = (const float*)d_in[8];
    const float* b2  = (const float*)d_in[9];
    float* out = (float*)d_out;

    const int n     = in_sizes[0] / D;
    const int e_raw = in_sizes[1] / 2;
    const int e_tot = e_raw + n;

    float *h1, *h2, *es1, *ed1, *es2, *ed2;
    __nv_bfloat16 *xh, *xl, *gh, *gl, *w1h, *w1l, *w2h, *w2l;
    cudaGetSymbolAddress((void**)&h1,  g_h1);
    cudaGetSymbolAddress((void**)&h2,  g_h2);
    cudaGetSymbolAddress((void**)&es1, g_es1);
    cudaGetSymbolAddress((void**)&ed1, g_ed1);
    cudaGetSymbolAddress((void**)&es2, g_es2);
    cudaGetSymbolAddress((void**)&ed2, g_ed2);
    cudaGetSymbolAddress((void**)&xh,  g_xh);
    cudaGetSymbolAddress((void**)&xl,  g_xl);
    cudaGetSymbolAddress((void**)&gh,  g_gh);
    cudaGetSymbolAddress((void**)&gl,  g_gl);
    cudaGetSymbolAddress((void**)&w1h, g_w1h);
    cudaGetSymbolAddress((void**)&w1l, g_w1l);
    cudaGetSymbolAddress((void**)&w2h, g_w2h);
    cudaGetSymbolAddress((void**)&w2l, g_w2l);

    cudaFuncSetAttribute(gemm_mma_kernel, cudaFuncAttributeMaxDynamicSharedMemorySize, GEMM_SMEM);

    // --- zero + CSR by dst (with self loops appended) ---
    zero_kernel<<<(n + 255) / 256, 256>>>(n);
    hist_kernel<<<(e_tot + 255) / 256, 256>>>(ei, e_raw, n);
    scan_kernel<<<1, 1024>>>(n);
    scatter_kernel<<<(e_tot + 255) / 256, 256>>>(ei, e_raw, n);

    // --- precision splits ---
    split_kernel<<<(n * D + 255) / 256, 256>>>(x, xh, xl, n * D);
    dim3 tgrid(D / 32, D / 32);
    transpose_split_kernel<<<tgrid, dim3(32, 8)>>>(W1, w1h, w1l);
    transpose_split_kernel<<<tgrid, dim3(32, 8)>>>(W2, w2h, w2l);

    dim3 gemm_grid(D / 128, (n + 127) / 128);

    // --- layer 1 ---
    gemm_mma_kernel<<<gemm_grid, 256, GEMM_SMEM>>>(xh, xl, w1h, w1l, h1, as1, ad1, es1, ed1, n);
    agg1_kernel<<<n, 256>>>(h1, b1, es1, ed1, gh, gl);

    // --- layer 2 ---
    gemm_mma_kernel<<<gemm_grid, 256, GEMM_SMEM>>>(gh, gl, w2h, w2l, h2, as2, ad2, es2, ed2, n);
    agg2_kernel<<<n, 256>>>(h2, b2, es2, ed2, out);
}

// round 5
// speedup vs baseline: 2.7616x; 1.2014x over previous
#include <cuda_runtime.h>
#include <cuda_fp16.h>
#include <cstdint>
#include <math.h>

#define D 768
#define N_MAX 10000
#define E_RAW_MAX 100000
#define E_TOT_MAX (E_RAW_MAX + N_MAX)

// ---------------- scratch (device globals; no allocation allowed) ----------------
__device__ float g_h1[(size_t)N_MAX * D];
__device__ float g_h2[(size_t)N_MAX * D];
__device__ __half g_xh[(size_t)N_MAX * D];          // fp16(x)
__device__ __half g_gh[(size_t)N_MAX * D];          // fp16(relu(layer1 out))
__device__ __half g_w1h[D * D], g_w1l[D * D];       // W1^T fp16 hi/lo
__device__ __half g_w2h[D * D], g_w2l[D * D];       // W2^T fp16 hi/lo
__device__ float g_es1[N_MAX], g_ed1[N_MAX];
__device__ float g_es2[N_MAX], g_ed2[N_MAX];
__device__ int   g_off[N_MAX + 1];
__device__ int   g_cur[N_MAX];
__device__ int   g_csr_src[E_TOT_MAX];

// ================= helpers =================
__device__ __forceinline__ uint32_t smem_u32(const void* p) {
    uint32_t a;
    asm("{ .reg .u64 t; cvta.to.shared.u64 t, %1; cvt.u32.u64 %0, t; }" : "=r"(a) : "l"(p));
    return a;
}
__device__ __forceinline__ uint32_t sw128(uint32_t x) { return x ^ ((x >> 3) & 0x70); }

__device__ __forceinline__ void cp_async16(uint32_t dst, const void* src) {
    asm volatile("cp.async.cg.shared.global [%0], [%1], 16;" :: "r"(dst), "l"(src) : "memory");
}
__device__ __forceinline__ void ldsm4(uint32_t* r, uint32_t addr) {
    asm volatile("ldmatrix.sync.aligned.m8n8.x4.shared.b16 {%0,%1,%2,%3}, [%4];"
                 : "=r"(r[0]), "=r"(r[1]), "=r"(r[2]), "=r"(r[3]) : "r"(addr));
}
__device__ __forceinline__ void mma_fp16(float* c, const uint32_t* a, const uint32_t* b) {
    asm volatile("mma.sync.aligned.m16n8k16.row.col.f32.f16.f16.f32 "
                 "{%0,%1,%2,%3}, {%4,%5,%6,%7}, {%8,%9}, {%0,%1,%2,%3};"
                 : "+f"(c[0]), "+f"(c[1]), "+f"(c[2]), "+f"(c[3])
                 : "r"(a[0]), "r"(a[1]), "r"(a[2]), "r"(a[3]), "r"(b[0]), "r"(b[1]));
}

// ---------------- zero: cursors + dot accumulators ----------------
__global__ void zero_kernel(int n) {
    int i = blockIdx.x * blockDim.x + threadIdx.x;
    if (i < n) {
        g_cur[i] = 0;
        g_es1[i] = 0.f; g_ed1[i] = 0.f;
        g_es2[i] = 0.f; g_ed2[i] = 0.f;
    }
}
__global__ void hist_kernel(const int* __restrict__ ei, int e_raw, int n) {
    int e = blockIdx.x * blockDim.x + threadIdx.x;
    int e_tot = e_raw + n;
    if (e >= e_tot) return;
    int dst = (e < e_raw) ? ei[e_raw + e] : (e - e_raw);
    atomicAdd(&g_cur[dst], 1);
}
__global__ void scan_kernel(int n) {
    __shared__ int sh[1024];
    __shared__ int s_carry;
    int tid = threadIdx.x;
    if (tid == 0) s_carry = 0;
    __syncthreads();
    for (int base = 0; base < n; base += 1024) {
        int i = base + tid;
        int v = (i < n) ? g_cur[i] : 0;
        sh[tid] = v;
        __syncthreads();
        for (int off = 1; off < 1024; off <<= 1) {
            int t = (tid >= off) ? sh[tid - off] : 0;
            __syncthreads();
            sh[tid] += t;
            __syncthreads();
        }
        int excl = sh[tid] - v;
        int carry = s_carry;
        if (i < n) { g_off[i] = carry + excl; g_cur[i] = carry + excl; }
        __syncthreads();
        if (tid == 1023) s_carry = carry + sh[1023];
        __syncthreads();
    }
    if (tid == 0) g_off[n] = s_carry;
}
__global__ void scatter_kernel(const int* __restrict__ ei, int e_raw, int n) {
    int e = blockIdx.x * blockDim.x + threadIdx.x;
    int e_tot = e_raw + n;
    if (e >= e_tot) return;
    int src = (e < e_raw) ? ei[e]         : (e - e_raw);
    int dst = (e < e_raw) ? ei[e_raw + e] : (e - e_raw);
    int pos = atomicAdd(&g_cur[dst], 1);
    g_csr_src[pos] = src;
}

// ---------------- fp32 -> fp16 ----------------
__global__ void split_kernel(const float* __restrict__ x,
                             __half* __restrict__ xh, int total) {
    int i = blockIdx.x * blockDim.x + threadIdx.x;
    if (i < total) xh[i] = __float2half(x[i]);
}

// ---------------- W[k][n] -> Wt[n][k], split to fp16 hi/lo ----------------
__global__ void transpose_split_kernel(const float* __restrict__ W,
                                       __half* __restrict__ Th,
                                       __half* __restrict__ Tl) {
    __shared__ float sh[32][33];
    int n0 = blockIdx.x * 32, k0 = blockIdx.y * 32;
    int tx = threadIdx.x, ty = threadIdx.y;
#pragma unroll
    for (int j = 0; j < 32; j += 8)
        sh[ty + j][tx] = W[(size_t)(k0 + ty + j) * D + n0 + tx];
    __syncthreads();
#pragma unroll
    for (int j = 0; j < 32; j += 8) {
        float v = sh[tx][ty + j];
        __half h = __float2half(v);
        size_t idx = (size_t)(n0 + ty + j) * D + k0 + tx;
        Th[idx] = h;
        Tl[idx] = __float2half(v - __half2float(h));
    }
}

// ---------------- tensor-core GEMM + fused attention dots ----------------
// C = Ah @ (Bh+Bl)^T ; also es[m] += C[m,:].a_src, ed[m] += C[m,:].a_dst
// CTA tile 128x128, 8 warps (2M x 4N), warp tile 64x32, K-chunk 64, 3-stage cp.async.
// SMEM stage: Ah(16K) Bh(16K) Bl(16K) = 48KB; 3 stages = 144KB.
#define STAGE_BYTES 49152
#define GEMM_SMEM (3 * STAGE_BYTES)

__global__ __launch_bounds__(256, 1)
void gemm_mma_kernel(const __half* __restrict__ Ah,
                     const __half* __restrict__ Bh,
                     const __half* __restrict__ Bl,
                     float* __restrict__ C,
                     const float* __restrict__ a_src,
                     const float* __restrict__ a_dst,
                     float* __restrict__ es, float* __restrict__ ed,
                     int M) {
    extern __shared__ __align__(1024) char smem[];
    const uint32_t sb = smem_u32(smem);
    const int tid  = threadIdx.x;
    const int wid  = tid >> 5;
    const int lane = tid & 31;
    const int m0 = blockIdx.y * 128;
    const int n0 = blockIdx.x * 128;
    const int warp_m = (wid & 1) * 64;
    const int warp_n = (wid >> 1) * 32;

    float acc[4][4][4];
#pragma unroll
    for (int i = 0; i < 4; i++)
#pragma unroll
        for (int j = 0; j < 4; j++)
#pragma unroll
            for (int k = 0; k < 4; k++) acc[i][j][k] = 0.f;

    auto issue_chunk = [&](int c) {
        const uint32_t st = sb + (uint32_t)(c % 3) * STAGE_BYTES;
        const int kc0 = c * 64;
#pragma unroll
        for (int i = 0; i < 4; i++) {
            int idx = i * 256 + tid;
            int row = idx >> 3, cc = idx & 7;
            uint32_t so = sw128((uint32_t)(row * 128 + cc * 16));
            int m = m0 + row; if (m >= M) m = M - 1;   // clamp: rows >= M never stored
            cp_async16(st + 0     + so, Ah + (size_t)m * D + kc0 + cc * 8);
            const size_t gb = (size_t)(n0 + row) * D + kc0 + cc * 8;
            cp_async16(st + 16384 + so, Bh + gb);
            cp_async16(st + 32768 + so, Bl + gb);
        }
    };

    issue_chunk(0);
    asm volatile("cp.async.commit_group;" ::: "memory");
    issue_chunk(1);
    asm volatile("cp.async.commit_group;" ::: "memory");

#pragma unroll 1
    for (int c = 0; c < 12; c++) {
        if (c + 2 < 12) {
            issue_chunk(c + 2);
            asm volatile("cp.async.commit_group;" ::: "memory");
            asm volatile("cp.async.wait_group 2;" ::: "memory");
        } else if (c + 1 < 12) {
            asm volatile("cp.async.wait_group 1;" ::: "memory");
        } else {
            asm volatile("cp.async.wait_group 0;" ::: "memory");
        }
        __syncthreads();

        const uint32_t st = sb + (uint32_t)(c % 3) * STAGE_BYTES;
#pragma unroll
        for (int ks = 0; ks < 4; ks++) {
            uint32_t af[4][4], bfh[2][4], bfl[2][4];
            const int arow = lane & 15;
            const int acol = (ks * 16 + (lane >> 4) * 8) * 2;
#pragma unroll
            for (int mt = 0; mt < 4; mt++) {
                uint32_t off = sw128((uint32_t)((warp_m + mt * 16 + arow) * 128 + acol));
                ldsm4(af[mt], st + off);
            }
            const int brow = (lane & 7) + ((lane >> 4) << 3);
            const int bcol = (ks * 16 + ((lane >> 3) & 1) * 8) * 2;
#pragma unroll
            for (int p = 0; p < 2; p++) {
                uint32_t off = sw128((uint32_t)((warp_n + p * 16 + brow) * 128 + bcol));
                ldsm4(bfh[p], st + 16384 + off);
                ldsm4(bfl[p], st + 32768 + off);
            }
#pragma unroll
            for (int mt = 0; mt < 4; mt++) {
#pragma unroll
                for (int nt = 0; nt < 4; nt++) {
                    const uint32_t* bh = &bfh[nt >> 1][(nt & 1) * 2];
                    const uint32_t* bl = &bfl[nt >> 1][(nt & 1) * 2];
                    mma_fp16(acc[mt][nt], af[mt], bh);
                    mma_fp16(acc[mt][nt], af[mt], bl);
                }
            }
        }
        __syncthreads();
    }

    // epilogue: store C + fused dot partials (quad shuffle reduce + atomicAdd)
    const int er = lane >> 2;
    const int ec = (lane & 3) * 2;
#pragma unroll
    for (int mt = 0; mt < 4; mt++) {
        int row = m0 + warp_m + mt * 16 + er;
        float s0 = 0.f, d0 = 0.f, s1 = 0.f, d1 = 0.f;
#pragma unroll
        for (int nt = 0; nt < 4; nt++) {
            int col = n0 + warp_n + nt * 8 + ec;
            if (row < M)
                *(float2*)(C + (size_t)row * D + col) = make_float2(acc[mt][nt][0], acc[mt][nt][1]);
            if (row + 8 < M)
                *(float2*)(C + (size_t)(row + 8) * D + col) = make_float2(acc[mt][nt][2], acc[mt][nt][3]);
            float as0 = __ldg(a_src + col), as1 = __ldg(a_src + col + 1);
            float ad0 = __ldg(a_dst + col), ad1 = __ldg(a_dst + col + 1);
            s0 = fmaf(acc[mt][nt][0], as0, fmaf(acc[mt][nt][1], as1, s0));
            d0 = fmaf(acc[mt][nt][0], ad0, fmaf(acc[mt][nt][1], ad1, d0));
            s1 = fmaf(acc[mt][nt][2], as0, fmaf(acc[mt][nt][3], as1, s1));
            d1 = fmaf(acc[mt][nt][2], ad0, fmaf(acc[mt][nt][3], ad1, d1));
        }
#pragma unroll
        for (int o = 1; o < 4; o <<= 1) {
            s0 += __shfl_xor_sync(0xffffffffu, s0, o);
            d0 += __shfl_xor_sync(0xffffffffu, d0, o);
            s1 += __shfl_xor_sync(0xffffffffu, s1, o);
            d1 += __shfl_xor_sync(0xffffffffu, d1, o);
        }
        if ((lane & 3) == 0) {
            if (row < M)     { atomicAdd(&es[row],     s0); atomicAdd(&ed[row],     d0); }
            if (row + 8 < M) { atomicAdd(&es[row + 8], s1); atomicAdd(&ed[row + 8], d1); }
        }
    }
}

// ---------------- segment softmax + aggregation (layer 1: emit fp16, relu) -------
__global__ __launch_bounds__(256)
void agg1_kernel(const float* __restrict__ h, const float* __restrict__ bias,
                 const float* __restrict__ es, const float* __restrict__ ed,
                 __half* __restrict__ gh) {
    const int node = blockIdx.x;
    const int tid = threadIdx.x;
    const int beg = g_off[node];
    const int end = g_off[node + 1];
    const float edv = ed[node];

    float mx = -1e30f;
    for (int i = beg + tid; i < end; i += 256) {
        float e = es[g_csr_src[i]] + edv;
        e = (e > 0.f) ? e : 0.2f * e;
        mx = fmaxf(mx, e);
    }
    __shared__ float red[256];
    red[tid] = mx;
    __syncthreads();
#pragma unroll
    for (int o = 128; o; o >>= 1) {
        if (tid < o) red[tid] = fmaxf(red[tid], red[tid + o]);
        __syncthreads();
    }
    mx = red[0];

    float z = 0.f, a0 = 0.f, a1 = 0.f, a2 = 0.f;
    for (int i = beg; i < end; i++) {
        int s = __ldg(&g_csr_src[i]);
        float e = __ldg(&es[s]) + edv;
        e = (e > 0.f) ? e : 0.2f * e;
        float w = expf(e - mx);
        z += w;
        const float* hr = h + (size_t)s * D;
        a0 = fmaf(w, __ldg(hr + tid),       a0);
        a1 = fmaf(w, __ldg(hr + tid + 256), a1);
        a2 = fmaf(w, __ldg(hr + tid + 512), a2);
    }
    float inv = 1.f / z;
    float o0 = fmaxf(a0 * inv + bias[tid],       0.f);
    float o1 = fmaxf(a1 * inv + bias[tid + 256], 0.f);
    float o2 = fmaxf(a2 * inv + bias[tid + 512], 0.f);
    size_t rb = (size_t)node * D;
    gh[rb + tid]       = __float2half(o0);
    gh[rb + tid + 256] = __float2half(o1);
    gh[rb + tid + 512] = __float2half(o2);
}

// ---------------- segment softmax + aggregation (layer 2: fp32 out) ----------------
__global__ __launch_bounds__(256)
void agg2_kernel(const float* __restrict__ h, const float* __restrict__ bias,
                 const float* __restrict__ es, const float* __restrict__ ed,
                 float* __restrict__ out) {
    const int node = blockIdx.x;
    const int tid = threadIdx.x;
    const int beg = g_off[node];
    const int end = g_off[node + 1];
    const float edv = ed[node];

    float mx = -1e30f;
    for (int i = beg + tid; i < end; i += 256) {
        float e = es[g_csr_src[i]] + edv;
        e = (e > 0.f) ? e : 0.2f * e;
        mx = fmaxf(mx, e);
    }
    __shared__ float red[256];
    red[tid] = mx;
    __syncthreads();
#pragma unroll
    for (int o = 128; o; o >>= 1) {
        if (tid < o) red[tid] = fmaxf(red[tid], red[tid + o]);
        __syncthreads();
    }
    mx = red[0];

    float z = 0.f, a0 = 0.f, a1 = 0.f, a2 = 0.f;
    for (int i = beg; i < end; i++) {
        int s = __ldg(&g_csr_src[i]);
        float e = __ldg(&es[s]) + edv;
        e = (e > 0.f) ? e : 0.2f * e;
        float w = expf(e - mx);
        z += w;
        const float* hr = h + (size_t)s * D;
        a0 = fmaf(w, __ldg(hr + tid),       a0);
        a1 = fmaf(w, __ldg(hr + tid + 256), a1);
        a2 = fmaf(w, __ldg(hr + tid + 512), a2);
    }
    float inv = 1.f / z;
    float* orow = out + (size_t)node * D;
    orow[tid]       = a0 * inv + bias[tid];
    orow[tid + 256] = a1 * inv + bias[tid + 256];
    orow[tid + 512] = a2 * inv + bias[tid + 512];
}

// ---------------- launch ----------------
extern "C" void kernel_launch(void* const* d_in, const int* in_sizes, int n_in,
                              void* d_out, int out_size) {
    const float* x   = (const float*)d_in[0];
    const int*   ei  = (const int*)  d_in[1];
    const float* W1  = (const float*)d_in[2];
    const float* as1 = (const float*)d_in[3];
    const float* ad1 = (const float*)d_in[4];
    const float* b1  = (const float*)d_in[5];
    const float* W2  = (const float*)d_in[6];
    const float* as2 = (const float*)d_in[7];
    const float* ad2 = (const float*)d_in[8];
    const float* b2  = (const float*)d_in[9];
    float* out = (float*)d_out;

    const int n     = in_sizes[0] / D;
    const int e_raw = in_sizes[1] / 2;
    const int e_tot = e_raw + n;

    float *h1, *h2, *es1, *ed1, *es2, *ed2;
    __half *xh, *gh, *w1h, *w1l, *w2h, *w2l;
    cudaGetSymbolAddress((void**)&h1,  g_h1);
    cudaGetSymbolAddress((void**)&h2,  g_h2);
    cudaGetSymbolAddress((void**)&es1, g_es1);
    cudaGetSymbolAddress((void**)&ed1, g_ed1);
    cudaGetSymbolAddress((void**)&es2, g_es2);
    cudaGetSymbolAddress((void**)&ed2, g_ed2);
    cudaGetSymbolAddress((void**)&xh,  g_xh);
    cudaGetSymbolAddress((void**)&gh,  g_gh);
    cudaGetSymbolAddress((void**)&w1h, g_w1h);
    cudaGetSymbolAddress((void**)&w1l, g_w1l);
    cudaGetSymbolAddress((void**)&w2h, g_w2h);
    cudaGetSymbolAddress((void**)&w2l, g_w2l);

    cudaFuncSetAttribute(gemm_mma_kernel, cudaFuncAttributeMaxDynamicSharedMemorySize, GEMM_SMEM);

    // --- zero + CSR by dst (with self loops appended) ---
    zero_kernel<<<(n + 255) / 256, 256>>>(n);
    hist_kernel<<<(e_tot + 255) / 256, 256>>>(ei, e_raw, n);
    scan_kernel<<<1, 1024>>>(n);
    scatter_kernel<<<(e_tot + 255) / 256, 256>>>(ei, e_raw, n);

    // --- precision conversion ---
    split_kernel<<<(n * D + 255) / 256, 256>>>(x, xh, n * D);
    dim3 tgrid(D / 32, D / 32);
    transpose_split_kernel<<<tgrid, dim3(32, 8)>>>(W1, w1h, w1l);
    transpose_split_kernel<<<tgrid, dim3(32, 8)>>>(W2, w2h, w2l);

    dim3 gemm_grid(D / 128, (n + 127) / 128);

    // --- layer 1 ---
    gemm_mma_kernel<<<gemm_grid, 256, GEMM_SMEM>>>(xh, w1h, w1l, h1, as1, ad1, es1, ed1, n);
    agg1_kernel<<<n, 256>>>(h1, b1, es1, ed1, gh);

    // --- layer 2 ---
    gemm_mma_kernel<<<gemm_grid, 256, GEMM_SMEM>>>(gh, w2h, w2l, h2, as2, ad2, es2, ed2, n);
    agg2_kernel<<<n, 256>>>(h2, b2, es2, ed2, out);
}

// round 6
// speedup vs baseline: 3.1203x; 1.1299x over previous
#include <cuda_runtime.h>
#include <cuda_fp16.h>
#include <cstdint>
#include <math.h>

#define D 768
#define N_MAX 10000
#define E_RAW_MAX 100000
#define E_TOT_MAX (E_RAW_MAX + N_MAX)

// ---------------- scratch (device globals; no allocation allowed) ----------------
__device__ __half g_h1[(size_t)N_MAX * D];          // layer1 GEMM out (fp16)
__device__ __half g_h2[(size_t)N_MAX * D];          // layer2 GEMM out (fp16)
__device__ __half g_xh[(size_t)N_MAX * D];          // fp16(x)
__device__ __half g_gh[(size_t)N_MAX * D];          // fp16(relu(layer1 out))
__device__ __half g_w1h[D * D];                     // W1^T fp16
__device__ __half g_w2h[D * D];                     // W2^T fp16
__device__ float g_es1[N_MAX], g_ed1[N_MAX];
__device__ float g_es2[N_MAX], g_ed2[N_MAX];
__device__ int   g_off[N_MAX + 1];
__device__ int   g_cur[N_MAX];
__device__ int   g_csr_src[E_TOT_MAX];

// ================= helpers =================
__device__ __forceinline__ uint32_t smem_u32(const void* p) {
    uint32_t a;
    asm("{ .reg .u64 t; cvta.to.shared.u64 t, %1; cvt.u32.u64 %0, t; }" : "=r"(a) : "l"(p));
    return a;
}
__device__ __forceinline__ uint32_t sw128(uint32_t x) { return x ^ ((x >> 3) & 0x70); }

__device__ __forceinline__ void cp_async16(uint32_t dst, const void* src) {
    asm volatile("cp.async.cg.shared.global [%0], [%1], 16;" :: "r"(dst), "l"(src) : "memory");
}
__device__ __forceinline__ void ldsm4(uint32_t* r, uint32_t addr) {
    asm volatile("ldmatrix.sync.aligned.m8n8.x4.shared.b16 {%0,%1,%2,%3}, [%4];"
                 : "=r"(r[0]), "=r"(r[1]), "=r"(r[2]), "=r"(r[3]) : "r"(addr));
}
__device__ __forceinline__ void mma_fp16(float* c, const uint32_t* a, const uint32_t* b) {
    asm volatile("mma.sync.aligned.m16n8k16.row.col.f32.f16.f16.f32 "
                 "{%0,%1,%2,%3}, {%4,%5,%6,%7}, {%8,%9}, {%0,%1,%2,%3};"
                 : "+f"(c[0]), "+f"(c[1]), "+f"(c[2]), "+f"(c[3])
                 : "r"(a[0]), "r"(a[1]), "r"(a[2]), "r"(a[3]), "r"(b[0]), "r"(b[1]));
}

// ---------------- zero: cursors + dot accumulators ----------------
__global__ void zero_kernel(int n) {
    int i = blockIdx.x * blockDim.x + threadIdx.x;
    if (i < n) {
        g_cur[i] = 0;
        g_es1[i] = 0.f; g_ed1[i] = 0.f;
        g_es2[i] = 0.f; g_ed2[i] = 0.f;
    }
}
__global__ void hist_kernel(const int* __restrict__ ei, int e_raw, int n) {
    int e = blockIdx.x * blockDim.x + threadIdx.x;
    int e_tot = e_raw + n;
    if (e >= e_tot) return;
    int dst = (e < e_raw) ? ei[e_raw + e] : (e - e_raw);
    atomicAdd(&g_cur[dst], 1);
}
__global__ void scan_kernel(int n) {
    __shared__ int sh[1024];
    __shared__ int s_carry;
    int tid = threadIdx.x;
    if (tid == 0) s_carry = 0;
    __syncthreads();
    for (int base = 0; base < n; base += 1024) {
        int i = base + tid;
        int v = (i < n) ? g_cur[i] : 0;
        sh[tid] = v;
        __syncthreads();
        for (int off = 1; off < 1024; off <<= 1) {
            int t = (tid >= off) ? sh[tid - off] : 0;
            __syncthreads();
            sh[tid] += t;
            __syncthreads();
        }
        int excl = sh[tid] - v;
        int carry = s_carry;
        if (i < n) { g_off[i] = carry + excl; g_cur[i] = carry + excl; }
        __syncthreads();
        if (tid == 1023) s_carry = carry + sh[1023];
        __syncthreads();
    }
    if (tid == 0) g_off[n] = s_carry;
}
__global__ void scatter_kernel(const int* __restrict__ ei, int e_raw, int n) {
    int e = blockIdx.x * blockDim.x + threadIdx.x;
    int e_tot = e_raw + n;
    if (e >= e_tot) return;
    int src = (e < e_raw) ? ei[e]         : (e - e_raw);
    int dst = (e < e_raw) ? ei[e_raw + e] : (e - e_raw);
    int pos = atomicAdd(&g_cur[dst], 1);
    g_csr_src[pos] = src;
}

// ---------------- fp32 -> fp16 ----------------
__global__ void split_kernel(const float* __restrict__ x,
                             __half* __restrict__ xh, int total4) {
    int i = blockIdx.x * blockDim.x + threadIdx.x;
    if (i < total4) {
        float4 v = *(const float4*)(x + i * 4);
        __half2* o = (__half2*)(xh + i * 4);
        o[0] = __floats2half2_rn(v.x, v.y);
        o[1] = __floats2half2_rn(v.z, v.w);
    }
}

// ---------------- W[k][n] -> Wt[n][k] fp16 ----------------
__global__ void transpose_kernel(const float* __restrict__ W,
                                 __half* __restrict__ Th) {
    __shared__ float sh[32][33];
    int n0 = blockIdx.x * 32, k0 = blockIdx.y * 32;
    int tx = threadIdx.x, ty = threadIdx.y;
#pragma unroll
    for (int j = 0; j < 32; j += 8)
        sh[ty + j][tx] = W[(size_t)(k0 + ty + j) * D + n0 + tx];
    __syncthreads();
#pragma unroll
    for (int j = 0; j < 32; j += 8)
        Th[(size_t)(n0 + ty + j) * D + k0 + tx] = __float2half(sh[tx][ty + j]);
}

// ---------------- tensor-core GEMM (fp16 single pass) + fused attention dots --------
// C(fp16) = Ah @ Bh^T ; es[m] += C[m,:].a_src, ed[m] += C[m,:].a_dst (fp32 accum)
// CTA tile 128x128, 8 warps (2M x 4N), warp tile 64x32, K-chunk 64, 3-stage cp.async.
// SMEM stage: Ah(16K) + Bh(16K) = 32KB; 3 stages = 96KB.
#define STAGE_BYTES 32768
#define GEMM_SMEM (3 * STAGE_BYTES)

__global__ __launch_bounds__(256, 1)
void gemm_mma_kernel(const __half* __restrict__ Ah,
                     const __half* __restrict__ Bh,
                     __half* __restrict__ C,
                     const float* __restrict__ a_src,
                     const float* __restrict__ a_dst,
                     float* __restrict__ es, float* __restrict__ ed,
                     int M) {
    extern __shared__ __align__(1024) char smem[];
    const uint32_t sb = smem_u32(smem);
    const int tid  = threadIdx.x;
    const int wid  = tid >> 5;
    const int lane = tid & 31;
    const int m0 = blockIdx.y * 128;
    const int n0 = blockIdx.x * 128;
    const int warp_m = (wid & 1) * 64;
    const int warp_n = (wid >> 1) * 32;

    float acc[4][4][4];
#pragma unroll
    for (int i = 0; i < 4; i++)
#pragma unroll
        for (int j = 0; j < 4; j++)
#pragma unroll
            for (int k = 0; k < 4; k++) acc[i][j][k] = 0.f;

    auto issue_chunk = [&](int c) {
        const uint32_t st = sb + (uint32_t)(c % 3) * STAGE_BYTES;
        const int kc0 = c * 64;
#pragma unroll
        for (int i = 0; i < 4; i++) {
            int idx = i * 256 + tid;
            int row = idx >> 3, cc = idx & 7;
            uint32_t so = sw128((uint32_t)(row * 128 + cc * 16));
            int m = m0 + row; if (m >= M) m = M - 1;   // clamp: rows >= M never stored
            cp_async16(st + 0     + so, Ah + (size_t)m * D + kc0 + cc * 8);
            cp_async16(st + 16384 + so, Bh + (size_t)(n0 + row) * D + kc0 + cc * 8);
        }
    };

    issue_chunk(0);
    asm volatile("cp.async.commit_group;" ::: "memory");
    issue_chunk(1);
    asm volatile("cp.async.commit_group;" ::: "memory");

#pragma unroll 1
    for (int c = 0; c < 12; c++) {
        if (c + 2 < 12) {
            issue_chunk(c + 2);
            asm volatile("cp.async.commit_group;" ::: "memory");
            asm volatile("cp.async.wait_group 2;" ::: "memory");
        } else if (c + 1 < 12) {
            asm volatile("cp.async.wait_group 1;" ::: "memory");
        } else {
            asm volatile("cp.async.wait_group 0;" ::: "memory");
        }
        __syncthreads();

        const uint32_t st = sb + (uint32_t)(c % 3) * STAGE_BYTES;
#pragma unroll
        for (int ks = 0; ks < 4; ks++) {
            uint32_t af[4][4], bf[2][4];
            const int arow = lane & 15;
            const int acol = (ks * 16 + (lane >> 4) * 8) * 2;
#pragma unroll
            for (int mt = 0; mt < 4; mt++) {
                uint32_t off = sw128((uint32_t)((warp_m + mt * 16 + arow) * 128 + acol));
                ldsm4(af[mt], st + off);
            }
            const int brow = (lane & 7) + ((lane >> 4) << 3);
            const int bcol = (ks * 16 + ((lane >> 3) & 1) * 8) * 2;
#pragma unroll
            for (int p = 0; p < 2; p++) {
                uint32_t off = sw128((uint32_t)((warp_n + p * 16 + brow) * 128 + bcol));
                ldsm4(bf[p], st + 16384 + off);
            }
#pragma unroll
            for (int mt = 0; mt < 4; mt++) {
#pragma unroll
                for (int nt = 0; nt < 4; nt++)
                    mma_fp16(acc[mt][nt], af[mt], &bf[nt >> 1][(nt & 1) * 2]);
            }
        }
        __syncthreads();
    }

    // epilogue: store C (fp16) + fused dot partials (quad shuffle reduce + atomicAdd)
    const int er = lane >> 2;
    const int ec = (lane & 3) * 2;
#pragma unroll
    for (int mt = 0; mt < 4; mt++) {
        int row = m0 + warp_m + mt * 16 + er;
        float s0 = 0.f, d0 = 0.f, s1 = 0.f, d1 = 0.f;
#pragma unroll
        for (int nt = 0; nt < 4; nt++) {
            int col = n0 + warp_n + nt * 8 + ec;
            if (row < M)
                *(__half2*)(C + (size_t)row * D + col) =
                    __floats2half2_rn(acc[mt][nt][0], acc[mt][nt][1]);
            if (row + 8 < M)
                *(__half2*)(C + (size_t)(row + 8) * D + col) =
                    __floats2half2_rn(acc[mt][nt][2], acc[mt][nt][3]);
            float as0 = __ldg(a_src + col), as1 = __ldg(a_src + col + 1);
            float ad0 = __ldg(a_dst + col), ad1 = __ldg(a_dst + col + 1);
            s0 = fmaf(acc[mt][nt][0], as0, fmaf(acc[mt][nt][1], as1, s0));
            d0 = fmaf(acc[mt][nt][0], ad0, fmaf(acc[mt][nt][1], ad1, d0));
            s1 = fmaf(acc[mt][nt][2], as0, fmaf(acc[mt][nt][3], as1, s1));
            d1 = fmaf(acc[mt][nt][2], ad0, fmaf(acc[mt][nt][3], ad1, d1));
        }
#pragma unroll
        for (int o = 1; o < 4; o <<= 1) {
            s0 += __shfl_xor_sync(0xffffffffu, s0, o);
            d0 += __shfl_xor_sync(0xffffffffu, d0, o);
            s1 += __shfl_xor_sync(0xffffffffu, s1, o);
            d1 += __shfl_xor_sync(0xffffffffu, d1, o);
        }
        if ((lane & 3) == 0) {
            if (row < M)     { atomicAdd(&es[row],     s0); atomicAdd(&ed[row],     d0); }
            if (row + 8 < M) { atomicAdd(&es[row + 8], s1); atomicAdd(&ed[row + 8], d1); }
        }
    }
}

// ---------------- segment softmax + aggregation ----------------
// 384 threads; thread t owns dims 2t, 2t+1 (one half2). h is fp16.
// MODE 0: out = alpha-weighted sum + bias (fp32 write, layer 2)
// MODE 1: relu(...) -> fp16 write (layer 1 -> g)
template <int MODE>
__global__ __launch_bounds__(384)
void agg_kernel(const __half* __restrict__ h, const float* __restrict__ bias,
                const float* __restrict__ es, const float* __restrict__ ed,
                void* __restrict__ outp) {
    const int node = blockIdx.x;
    const int tid = threadIdx.x;
    const int beg = g_off[node];
    const int end = g_off[node + 1];
    const float edv = ed[node];

    float mx = -1e30f;
    for (int i = beg + tid; i < end; i += 384) {
        float e = es[g_csr_src[i]] + edv;
        e = (e > 0.f) ? e : 0.2f * e;
        mx = fmaxf(mx, e);
    }
    __shared__ float red[512];
    red[tid] = mx;
    if (tid < 128) red[384 + tid] = -1e30f;
    __syncthreads();
#pragma unroll
    for (int o = 256; o; o >>= 1) {
        if (tid < o && tid + o < 512) red[tid] = fmaxf(red[tid], red[tid + o]);
        __syncthreads();
    }
    mx = red[0];

    float z = 0.f, ax = 0.f, ay = 0.f;
    for (int i = beg; i < end; i++) {
        int s = __ldg(&g_csr_src[i]);
        float e = __ldg(&es[s]) + edv;
        e = (e > 0.f) ? e : 0.2f * e;
        float w = expf(e - mx);
        z += w;
        __half2 hv = __ldg((const __half2*)(h + (size_t)s * D) + tid);
        float2 hf = __half22float2(hv);
        ax = fmaf(w, hf.x, ax);
        ay = fmaf(w, hf.y, ay);
    }
    float inv = 1.f / z;
    float ox = ax * inv + bias[2 * tid];
    float oy = ay * inv + bias[2 * tid + 1];
    if (MODE == 1) {
        ox = fmaxf(ox, 0.f);
        oy = fmaxf(oy, 0.f);
        ((__half2*)outp)[(size_t)node * (D / 2) + tid] = __floats2half2_rn(ox, oy);
    } else {
        ((float2*)outp)[(size_t)node * (D / 2) + tid] = make_float2(ox, oy);
    }
}

// ---------------- launch ----------------
extern "C" void kernel_launch(void* const* d_in, const int* in_sizes, int n_in,
                              void* d_out, int out_size) {
    const float* x   = (const float*)d_in[0];
    const int*   ei  = (const int*)  d_in[1];
    const float* W1  = (const float*)d_in[2];
    const float* as1 = (const float*)d_in[3];
    const float* ad1 = (const float*)d_in[4];
    const float* b1  = (const float*)d_in[5];
    const float* W2  = (const float*)d_in[6];
    const float* as2 = (const float*)d_in[7];
    const float* ad2 = (const float*)d_in[8];
    const float* b2  = (const float*)d_in[9];
    float* out = (float*)d_out;

    const int n     = in_sizes[0] / D;
    const int e_raw = in_sizes[1] / 2;
    const int e_tot = e_raw + n;

    float *es1, *ed1, *es2, *ed2;
    __half *h1, *h2, *xh, *gh, *w1h, *w2h;
    cudaGetSymbolAddress((void**)&h1,  g_h1);
    cudaGetSymbolAddress((void**)&h2,  g_h2);
    cudaGetSymbolAddress((void**)&es1, g_es1);
    cudaGetSymbolAddress((void**)&ed1, g_ed1);
    cudaGetSymbolAddress((void**)&es2, g_es2);
    cudaGetSymbolAddress((void**)&ed2, g_ed2);
    cudaGetSymbolAddress((void**)&xh,  g_xh);
    cudaGetSymbolAddress((void**)&gh,  g_gh);
    cudaGetSymbolAddress((void**)&w1h, g_w1h);
    cudaGetSymbolAddress((void**)&w2h, g_w2h);

    cudaFuncSetAttribute(gemm_mma_kernel, cudaFuncAttributeMaxDynamicSharedMemorySize, GEMM_SMEM);

    // --- zero + CSR by dst (with self loops appended) ---
    zero_kernel<<<(n + 255) / 256, 256>>>(n);
    hist_kernel<<<(e_tot + 255) / 256, 256>>>(ei, e_raw, n);
    scan_kernel<<<1, 1024>>>(n);
    scatter_kernel<<<(e_tot + 255) / 256, 256>>>(ei, e_raw, n);

    // --- precision conversion ---
    split_kernel<<<(n * D / 4 + 255) / 256, 256>>>(x, xh, n * D / 4);
    dim3 tgrid(D / 32, D / 32);
    transpose_kernel<<<tgrid, dim3(32, 8)>>>(W1, w1h);
    transpose_kernel<<<tgrid, dim3(32, 8)>>>(W2, w2h);

    dim3 gemm_grid(D / 128, (n + 127) / 128);

    // --- layer 1 ---
    gemm_mma_kernel<<<gemm_grid, 256, GEMM_SMEM>>>(xh, w1h, h1, as1, ad1, es1, ed1, n);
    agg_kernel<1><<<n, 384>>>(h1, b1, es1, ed1, gh);

    // --- layer 2 ---
    gemm_mma_kernel<<<gemm_grid, 256, GEMM_SMEM>>>(gh, w2h, h2, as2, ad2, es2, ed2, n);
    agg_kernel<0><<<n, 384>>>(h2, b2, es2, ed2, out);
}

// round 7
// speedup vs baseline: 3.9821x; 1.2762x over previous
#include <cuda_runtime.h>
#include <cuda_fp16.h>
#include <cstdint>
#include <math.h>

#define D 768
#define N_MAX 10000
#define E_RAW_MAX 100000
#define E_TOT_MAX (E_RAW_MAX + N_MAX)

// ---------------- scratch (device globals; no allocation allowed) ----------------
__device__ __half g_h1[(size_t)N_MAX * D];          // layer1 GEMM out (fp16)
__device__ __half g_h2[(size_t)N_MAX * D];          // layer2 GEMM out (fp16)
__device__ __half g_xh[(size_t)N_MAX * D];          // fp16(x)
__device__ __half g_gh[(size_t)N_MAX * D];          // fp16(relu(layer1 out))
__device__ __half g_w1h[D * D];                     // W1^T fp16
__device__ __half g_w2h[D * D];                     // W2^T fp16
__device__ float g_es1[N_MAX], g_ed1[N_MAX];
__device__ float g_es2[N_MAX], g_ed2[N_MAX];
__device__ int   g_off[N_MAX + 1];
__device__ int   g_cur[N_MAX];
__device__ int   g_csr_src[E_TOT_MAX];
__device__ int   g_csr_dst[E_TOT_MAX];
__device__ float g_wbuf[E_TOT_MAX];

// ================= helpers =================
__device__ __forceinline__ uint32_t smem_u32(const void* p) {
    uint32_t a;
    asm("{ .reg .u64 t; cvta.to.shared.u64 t, %1; cvt.u32.u64 %0, t; }" : "=r"(a) : "l"(p));
    return a;
}
__device__ __forceinline__ uint32_t sw128(uint32_t x) { return x ^ ((x >> 3) & 0x70); }

__device__ __forceinline__ void cp_async16(uint32_t dst, const void* src) {
    asm volatile("cp.async.cg.shared.global [%0], [%1], 16;" :: "r"(dst), "l"(src) : "memory");
}
__device__ __forceinline__ void ldsm4(uint32_t* r, uint32_t addr) {
    asm volatile("ldmatrix.sync.aligned.m8n8.x4.shared.b16 {%0,%1,%2,%3}, [%4];"
                 : "=r"(r[0]), "=r"(r[1]), "=r"(r[2]), "=r"(r[3]) : "r"(addr));
}
__device__ __forceinline__ void mma_fp16(float* c, const uint32_t* a, const uint32_t* b) {
    asm volatile("mma.sync.aligned.m16n8k16.row.col.f32.f16.f16.f32 "
                 "{%0,%1,%2,%3}, {%4,%5,%6,%7}, {%8,%9}, {%0,%1,%2,%3};"
                 : "+f"(c[0]), "+f"(c[1]), "+f"(c[2]), "+f"(c[3])
                 : "r"(a[0]), "r"(a[1]), "r"(a[2]), "r"(a[3]), "r"(b[0]), "r"(b[1]));
}

// ---------------- zero: cursors + dot accumulators ----------------
__global__ void zero_kernel(int n) {
    int i = blockIdx.x * blockDim.x + threadIdx.x;
    if (i < n) {
        g_cur[i] = 0;
        g_es1[i] = 0.f; g_ed1[i] = 0.f;
        g_es2[i] = 0.f; g_ed2[i] = 0.f;
    }
}
__global__ void hist_kernel(const int* __restrict__ ei, int e_raw, int n) {
    int e = blockIdx.x * blockDim.x + threadIdx.x;
    int e_tot = e_raw + n;
    if (e >= e_tot) return;
    int dst = (e < e_raw) ? ei[e_raw + e] : (e - e_raw);
    atomicAdd(&g_cur[dst], 1);
}
__global__ void scan_kernel(int n) {
    __shared__ int sh[1024];
    __shared__ int s_carry;
    int tid = threadIdx.x;
    if (tid == 0) s_carry = 0;
    __syncthreads();
    for (int base = 0; base < n; base += 1024) {
        int i = base + tid;
        int v = (i < n) ? g_cur[i] : 0;
        sh[tid] = v;
        __syncthreads();
        for (int off = 1; off < 1024; off <<= 1) {
            int t = (tid >= off) ? sh[tid - off] : 0;
            __syncthreads();
            sh[tid] += t;
            __syncthreads();
        }
        int excl = sh[tid] - v;
        int carry = s_carry;
        if (i < n) { g_off[i] = carry + excl; g_cur[i] = carry + excl; }
        __syncthreads();
        if (tid == 1023) s_carry = carry + sh[1023];
        __syncthreads();
    }
    if (tid == 0) g_off[n] = s_carry;
}
__global__ void scatter_kernel(const int* __restrict__ ei, int e_raw, int n) {
    int e = blockIdx.x * blockDim.x + threadIdx.x;
    int e_tot = e_raw + n;
    if (e >= e_tot) return;
    int src = (e < e_raw) ? ei[e]         : (e - e_raw);
    int dst = (e < e_raw) ? ei[e_raw + e] : (e - e_raw);
    int pos = atomicAdd(&g_cur[dst], 1);
    g_csr_src[pos] = src;
    g_csr_dst[pos] = dst;
}

// ---------------- per-edge softmax weight (no max-sub; logits bounded) ----------------
__global__ void wcalc_kernel(const float* __restrict__ es, const float* __restrict__ ed,
                             int e_tot) {
    int i = blockIdx.x * blockDim.x + threadIdx.x;
    if (i >= e_tot) return;
    float e = __ldg(&es[g_csr_src[i]]) + __ldg(&ed[g_csr_dst[i]]);
    e = (e > 0.f) ? e : 0.2f * e;
    g_wbuf[i] = expf(e);
}

// ---------------- fp32 -> fp16 ----------------
__global__ void split_kernel(const float* __restrict__ x,
                             __half* __restrict__ xh, int total4) {
    int i = blockIdx.x * blockDim.x + threadIdx.x;
    if (i < total4) {
        float4 v = *(const float4*)(x + i * 4);
        __half2* o = (__half2*)(xh + i * 4);
        o[0] = __floats2half2_rn(v.x, v.y);
        o[1] = __floats2half2_rn(v.z, v.w);
    }
}

// ---------------- W[k][n] -> Wt[n][k] fp16 ----------------
__global__ void transpose_kernel(const float* __restrict__ W,
                                 __half* __restrict__ Th) {
    __shared__ float sh[32][33];
    int n0 = blockIdx.x * 32, k0 = blockIdx.y * 32;
    int tx = threadIdx.x, ty = threadIdx.y;
#pragma unroll
    for (int j = 0; j < 32; j += 8)
        sh[ty + j][tx] = W[(size_t)(k0 + ty + j) * D + n0 + tx];
    __syncthreads();
#pragma unroll
    for (int j = 0; j < 32; j += 8)
        Th[(size_t)(n0 + ty + j) * D + k0 + tx] = __float2half(sh[tx][ty + j]);
}

// ---------------- tensor-core GEMM (fp16 single pass) + fused attention dots --------
#define STAGE_BYTES 32768
#define GEMM_SMEM (3 * STAGE_BYTES)

__global__ __launch_bounds__(256, 1)
void gemm_mma_kernel(const __half* __restrict__ Ah,
                     const __half* __restrict__ Bh,
                     __half* __restrict__ C,
                     const float* __restrict__ a_src,
                     const float* __restrict__ a_dst,
                     float* __restrict__ es, float* __restrict__ ed,
                     int M) {
    extern __shared__ __align__(1024) char smem[];
    const uint32_t sb = smem_u32(smem);
    const int tid  = threadIdx.x;
    const int wid  = tid >> 5;
    const int lane = tid & 31;
    const int m0 = blockIdx.y * 128;
    const int n0 = blockIdx.x * 128;
    const int warp_m = (wid & 1) * 64;
    const int warp_n = (wid >> 1) * 32;

    float acc[4][4][4];
#pragma unroll
    for (int i = 0; i < 4; i++)
#pragma unroll
        for (int j = 0; j < 4; j++)
#pragma unroll
            for (int k = 0; k < 4; k++) acc[i][j][k] = 0.f;

    auto issue_chunk = [&](int c) {
        const uint32_t st = sb + (uint32_t)(c % 3) * STAGE_BYTES;
        const int kc0 = c * 64;
#pragma unroll
        for (int i = 0; i < 4; i++) {
            int idx = i * 256 + tid;
            int row = idx >> 3, cc = idx & 7;
            uint32_t so = sw128((uint32_t)(row * 128 + cc * 16));
            int m = m0 + row; if (m >= M) m = M - 1;   // clamp: rows >= M never stored
            cp_async16(st + 0     + so, Ah + (size_t)m * D + kc0 + cc * 8);
            cp_async16(st + 16384 + so, Bh + (size_t)(n0 + row) * D + kc0 + cc * 8);
        }
    };

    issue_chunk(0);
    asm volatile("cp.async.commit_group;" ::: "memory");
    issue_chunk(1);
    asm volatile("cp.async.commit_group;" ::: "memory");

#pragma unroll 1
    for (int c = 0; c < 12; c++) {
        if (c + 2 < 12) {
            issue_chunk(c + 2);
            asm volatile("cp.async.commit_group;" ::: "memory");
            asm volatile("cp.async.wait_group 2;" ::: "memory");
        } else if (c + 1 < 12) {
            asm volatile("cp.async.wait_group 1;" ::: "memory");
        } else {
            asm volatile("cp.async.wait_group 0;" ::: "memory");
        }
        __syncthreads();

        const uint32_t st = sb + (uint32_t)(c % 3) * STAGE_BYTES;
#pragma unroll
        for (int ks = 0; ks < 4; ks++) {
            uint32_t af[4][4], bf[2][4];
            const int arow = lane & 15;
            const int acol = (ks * 16 + (lane >> 4) * 8) * 2;
#pragma unroll
            for (int mt = 0; mt < 4; mt++) {
                uint32_t off = sw128((uint32_t)((warp_m + mt * 16 + arow) * 128 + acol));
                ldsm4(af[mt], st + off);
            }
            const int brow = (lane & 7) + ((lane >> 4) << 3);
            const int bcol = (ks * 16 + ((lane >> 3) & 1) * 8) * 2;
#pragma unroll
            for (int p = 0; p < 2; p++) {
                uint32_t off = sw128((uint32_t)((warp_n + p * 16 + brow) * 128 + bcol));
                ldsm4(bf[p], st + 16384 + off);
            }
#pragma unroll
            for (int mt = 0; mt < 4; mt++) {
#pragma unroll
                for (int nt = 0; nt < 4; nt++)
                    mma_fp16(acc[mt][nt], af[mt], &bf[nt >> 1][(nt & 1) * 2]);
            }
        }
        __syncthreads();
    }

    // epilogue: store C (fp16) + fused dot partials (quad shuffle reduce + atomicAdd)
    const int er = lane >> 2;
    const int ec = (lane & 3) * 2;
#pragma unroll
    for (int mt = 0; mt < 4; mt++) {
        int row = m0 + warp_m + mt * 16 + er;
        float s0 = 0.f, d0 = 0.f, s1 = 0.f, d1 = 0.f;
#pragma unroll
        for (int nt = 0; nt < 4; nt++) {
            int col = n0 + warp_n + nt * 8 + ec;
            if (row < M)
                *(__half2*)(C + (size_t)row * D + col) =
                    __floats2half2_rn(acc[mt][nt][0], acc[mt][nt][1]);
            if (row + 8 < M)
                *(__half2*)(C + (size_t)(row + 8) * D + col) =
                    __floats2half2_rn(acc[mt][nt][2], acc[mt][nt][3]);
            float as0 = __ldg(a_src + col), as1 = __ldg(a_src + col + 1);
            float ad0 = __ldg(a_dst + col), ad1 = __ldg(a_dst + col + 1);
            s0 = fmaf(acc[mt][nt][0], as0, fmaf(acc[mt][nt][1], as1, s0));
            d0 = fmaf(acc[mt][nt][0], ad0, fmaf(acc[mt][nt][1], ad1, d0));
            s1 = fmaf(acc[mt][nt][2], as0, fmaf(acc[mt][nt][3], as1, s1));
            d1 = fmaf(acc[mt][nt][2], ad0, fmaf(acc[mt][nt][3], ad1, d1));
        }
#pragma unroll
        for (int o = 1; o < 4; o <<= 1) {
            s0 += __shfl_xor_sync(0xffffffffu, s0, o);
            d0 += __shfl_xor_sync(0xffffffffu, d0, o);
            s1 += __shfl_xor_sync(0xffffffffu, s1, o);
            d1 += __shfl_xor_sync(0xffffffffu, d1, o);
        }
        if ((lane & 3) == 0) {
            if (row < M)     { atomicAdd(&es[row],     s0); atomicAdd(&ed[row],     d0); }
            if (row + 8 < M) { atomicAdd(&es[row + 8], s1); atomicAdd(&ed[row + 8], d1); }
        }
    }
}

// ---------------- segment aggregation (weights precomputed) ----------------
// 384 threads; thread t owns dims 2t, 2t+1. w[] contiguous per node.
// MODE 0: fp32 out + bias. MODE 1: relu -> fp16 out.
template <int MODE>
__global__ __launch_bounds__(384)
void agg_kernel(const __half* __restrict__ h, const float* __restrict__ bias,
                void* __restrict__ outp) {
    const int node = blockIdx.x;
    const int tid = threadIdx.x;
    const int beg = g_off[node];
    const int end = g_off[node + 1];

    float z = 0.f, ax = 0.f, ay = 0.f;
    for (int i = beg; i < end; i++) {
        float w = __ldg(&g_wbuf[i]);
        int s = __ldg(&g_csr_src[i]);
        z += w;
        __half2 hv = __ldg((const __half2*)(h + (size_t)s * D) + tid);
        float2 hf = __half22float2(hv);
        ax = fmaf(w, hf.x, ax);
        ay = fmaf(w, hf.y, ay);
    }
    float inv = 1.f / z;
    float ox = ax * inv + bias[2 * tid];
    float oy = ay * inv + bias[2 * tid + 1];
    if (MODE == 1) {
        ox = fmaxf(ox, 0.f);
        oy = fmaxf(oy, 0.f);
        ((__half2*)outp)[(size_t)node * (D / 2) + tid] = __floats2half2_rn(ox, oy);
    } else {
        ((float2*)outp)[(size_t)node * (D / 2) + tid] = make_float2(ox, oy);
    }
}

// ---------------- launch ----------------
extern "C" void kernel_launch(void* const* d_in, const int* in_sizes, int n_in,
                              void* d_out, int out_size) {
    const float* x   = (const float*)d_in[0];
    const int*   ei  = (const int*)  d_in[1];
    const float* W1  = (const float*)d_in[2];
    const float* as1 = (const float*)d_in[3];
    const float* ad1 = (const float*)d_in[4];
    const float* b1  = (const float*)d_in[5];
    const float* W2  = (const float*)d_in[6];
    const float* as2 = (const float*)d_in[7];
    const float* ad2 = (const float*)d_in[8];
    const float* b2  = (const float*)d_in[9];
    float* out = (float*)d_out;

    const int n     = in_sizes[0] / D;
    const int e_raw = in_sizes[1] / 2;
    const int e_tot = e_raw + n;

    float *es1, *ed1, *es2, *ed2;
    __half *h1, *h2, *xh, *gh, *w1h, *w2h;
    cudaGetSymbolAddress((void**)&h1,  g_h1);
    cudaGetSymbolAddress((void**)&h2,  g_h2);
    cudaGetSymbolAddress((void**)&es1, g_es1);
    cudaGetSymbolAddress((void**)&ed1, g_ed1);
    cudaGetSymbolAddress((void**)&es2, g_es2);
    cudaGetSymbolAddress((void**)&ed2, g_ed2);
    cudaGetSymbolAddress((void**)&xh,  g_xh);
    cudaGetSymbolAddress((void**)&gh,  g_gh);
    cudaGetSymbolAddress((void**)&w1h, g_w1h);
    cudaGetSymbolAddress((void**)&w2h, g_w2h);

    cudaFuncSetAttribute(gemm_mma_kernel, cudaFuncAttributeMaxDynamicSharedMemorySize, GEMM_SMEM);

    // streams/events for fork-join inside graph capture (created once, host-side only)
    static cudaStream_t s_csr = nullptr;
    static cudaEvent_t  e_fork = nullptr, e_csr = nullptr;
    if (!s_csr) {
        if (cudaStreamCreateWithFlags(&s_csr, cudaStreamNonBlocking) != cudaSuccess)
            s_csr = nullptr;
        cudaEventCreateWithFlags(&e_fork, cudaEventDisableTiming);
        cudaEventCreateWithFlags(&e_csr, cudaEventDisableTiming);
    }
    cudaStream_t cs = s_csr ? s_csr : (cudaStream_t)0;

    // fork
    if (s_csr) {
        cudaEventRecord(e_fork, 0);
        cudaStreamWaitEvent(cs, e_fork, 0);
    }

    // --- CSR chain on side stream ---
    zero_kernel<<<(n + 255) / 256, 256, 0, cs>>>(n);
    hist_kernel<<<(e_tot + 255) / 256, 256, 0, cs>>>(ei, e_raw, n);
    scan_kernel<<<1, 1024, 0, cs>>>(n);
    scatter_kernel<<<(e_tot + 255) / 256, 256, 0, cs>>>(ei, e_raw, n);
    if (s_csr) cudaEventRecord(e_csr, cs);

    // --- conversions + GEMM1 on main stream (zero_kernel also zeroes es/ed: csr stream
    //     must complete before gemm epilogue atomics -> wait placed before gemm1) ---
    split_kernel<<<(n * D / 4 + 255) / 256, 256>>>(x, xh, n * D / 4);
    dim3 tgrid(D / 32, D / 32);
    transpose_kernel<<<tgrid, dim3(32, 8)>>>(W1, w1h);
    transpose_kernel<<<tgrid, dim3(32, 8)>>>(W2, w2h);

    // join: gemm1 epilogue atomically accumulates into es1/ed1 (zeroed on csr stream)
    if (s_csr) cudaStreamWaitEvent((cudaStream_t)0, e_csr, 0);

    dim3 gemm_grid(D / 128, (n + 127) / 128);

    // --- layer 1 ---
    gemm_mma_kernel<<<gemm_grid, 256, GEMM_SMEM>>>(xh, w1h, h1, as1, ad1, es1, ed1, n);
    wcalc_kernel<<<(e_tot + 255) / 256, 256>>>(es1, ed1, e_tot);
    agg_kernel<1><<<n, 384>>>(h1, b1, gh);

    // --- layer 2 ---
    gemm_mma_kernel<<<gemm_grid, 256, GEMM_SMEM>>>(gh, w2h, h2, as2, ad2, es2, ed2, n);
    wcalc_kernel<<<(e_tot + 255) / 256, 256>>>(es2, ed2, e_tot);
    agg_kernel<0><<<n, 384>>>(h2, b2, out);
}